// round 13
// baseline (speedup 1.0000x reference)
#include <cuda_runtime.h>

#define BB 1024
#define PP 128
#define MM 127

typedef unsigned long long ull;

#define NPAIR 8256          // 128*129/2
#define KSPLIT 32
#define KPER 272            // per-split pair count (17 chunks of 16); 32*272 = 8704
#define NPAD (KSPLIT * KPER)

// ---------------------------------------------------------------------------
// Static device scratch (allocation-free)
// ---------------------------------------------------------------------------
__device__ float g_Upad[127 * 127 * 128];     // [t][s][k-pad]   8.3 MB
__device__ float g_W1s[NPAD * 128];           // [pair][k-pad]   4.5 MB (sym-folded)
__device__ int   g_pmap[NPAD];                // pair -> i*128+j (pad -> 0)
__device__ float g_z0p[32 * 1024 * 128];      // split-K partials
__device__ float g_z0[1024 * 128];            // [b][k-pad]
__device__ float g_dz[1024 * 127 * 128];      // [b][t][k-pad]  66.6 MB

// ---------------------------------------------------------------------------
// f32x2 packed-FMA helpers
// ---------------------------------------------------------------------------
__device__ __forceinline__ ull dup2(float x) {
    ull u; asm("mov.b64 %0, {%1, %1};" : "=l"(u) : "r"(__float_as_uint(x))); return u;
}
__device__ __forceinline__ void unpack2(ull u, float& lo, float& hi) {
    unsigned int a, b;
    asm("mov.b64 {%0, %1}, %2;" : "=r"(a), "=r"(b) : "l"(u));
    lo = __uint_as_float(a); hi = __uint_as_float(b);
}
__device__ __forceinline__ void fma2(ull& d, ull a, ull b) {
    asm("fma.rn.f32x2 %0, %1, %2, %0;" : "+l"(d) : "l"(a), "l"(b));
}

// 8 rows x 4 cols step (512 thr, tx=tid&31, ty=tid>>5) — used by z0s/g2out.
__device__ __forceinline__ void mma_step512(ull acc2[4][4],
                                            const float* __restrict__ Arow,
                                            const float* __restrict__ Bcol) {
    ulonglong2 aA = *(const ulonglong2*)(Arow);
    ulonglong2 aB = *(const ulonglong2*)(Arow + 4);
    float4 b = *(const float4*)(Bcol);
    ull a2[4] = {aA.x, aA.y, aB.x, aB.y};
    ull bd[4] = {dup2(b.x), dup2(b.y), dup2(b.z), dup2(b.w)};
#pragma unroll
    for (int i2 = 0; i2 < 4; i2++)
#pragma unroll
        for (int j = 0; j < 4; j++) fma2(acc2[i2][j], a2[i2], bd[j]);
}

// 8 rows x 8 cols step (LDS-balanced: 4 LDS.128 per 32 FFMA2) — used by dz.
__device__ __forceinline__ void mma_step88(ull acc2[4][8],
                                           const float* __restrict__ Arow,
                                           const float* __restrict__ Brow) {
    ulonglong2 aA = *(const ulonglong2*)(Arow);
    ulonglong2 aB = *(const ulonglong2*)(Arow + 4);
    float4 b0 = *(const float4*)(Brow);
    float4 b1 = *(const float4*)(Brow + 4);
    ull a2[4] = {aA.x, aA.y, aB.x, aB.y};
    ull bd[8];
    bd[0] = dup2(b0.x); bd[1] = dup2(b0.y); bd[2] = dup2(b0.z); bd[3] = dup2(b0.w);
    bd[4] = dup2(b1.x); bd[5] = dup2(b1.y); bd[6] = dup2(b1.z); bd[7] = dup2(b1.w);
#pragma unroll
    for (int i2 = 0; i2 < 4; i2++)
#pragma unroll
        for (int j = 0; j < 8; j++) fma2(acc2[i2][j], a2[i2], bd[j]);
}

// ---------------------------------------------------------------------------
// Merged builder: blocks [0,508) build U; [508,636) build W1s; [636,640) pmap.
// ---------------------------------------------------------------------------
__global__ void k_build(const float* __restrict__ W1) {
    int bx = blockIdx.x;
    int k = threadIdx.x;

    if (bx < 508) {                        // ---- U[t][s][k] ----
        int t = bx % 127;
        int s0 = (bx / 127) * 32;
        int s1 = s0 + 32 < 127 ? s0 + 32 : 127;
        float winf = (k < MM) ? W1[16256 * 127 + k] : 0.f;
        for (int s = s0; s < s1; s++) {
            float u = 0.f;
            if (k < MM) {
                if (s == t)
                    u = W1[(t * 127 + t) * 127 + k] - winf;
                else
                    u = W1[(t * 127 + s) * 127 + k]
                      + W1[(s * 127 + t) * 127 + k]
                      - W1[(16129 + s) * 127 + k];
            }
            g_Upad[(t * 127 + s) * 128 + k] = u;
        }
    } else if (bx < 636) {                 // ---- W1s[pair][k] (sym-folded) ----
        int i = bx - 508;
        int base = i * 128 - (i * (i - 1)) / 2;
        for (int j = i; j < 128; j++) {
            int p = base + (j - i);
            float v = 0.f;
            if (k < 127) {
                if (i == 0 && j == 0)      v = W1[16256 * 127 + k];
                else if (i == 0)           v = W1[(16129 + j - 1) * 127 + k];
                else if (i == j)           v = W1[((i - 1) * 127 + (i - 1)) * 127 + k];
                else                       v = W1[((i - 1) * 127 + (j - 1)) * 127 + k]
                                             + W1[((j - 1) * 127 + (i - 1)) * 127 + k];
            }
            g_W1s[p * 128 + k] = v;
        }
        for (int p = NPAIR + i; p < NPAD; p += 128)
            g_W1s[p * 128 + k] = 0.f;
    } else {                               // ---- pmap ----
        int i = (bx - 636) * 32 + (k >> 2);
        int lane = k & 3;
        if (i < 128) {
            int base = i * 128 - (i * (i - 1)) / 2;
            for (int j = i + lane; j < 128; j += 4)
                g_pmap[base + (j - i)] = i * 128 + j;
        }
        if (bx == 636) {
            for (int p = NPAIR + k; p < NPAD; p += 128) g_pmap[p] = 0;
        }
    }
}

// ---------------------------------------------------------------------------
// z0 GEMM (symmetric-packed): [1024, 8704] @ [8704, 128], split-K=32.
// ---------------------------------------------------------------------------
__global__ void __launch_bounds__(512, 2) k_z0s(const float* __restrict__ Theta) {
    extern __shared__ float sm[];
    float* As = sm;
    float* Bs = sm + 2 * 16 * 132;
    int* spmap = (int*)(sm + 2 * 16 * 132 + 2 * 16 * 128);
    const int tid = threadIdx.x, tx = tid & 31, ty = tid >> 5;
    const int b0 = blockIdx.x * 128;
    const int kbase = blockIdx.y * KPER;

    for (int q = tid; q < KPER; q += 512) spmap[q] = g_pmap[kbase + q];
    __syncthreads();

    ull acc2[4][4];
#pragma unroll
    for (int i = 0; i < 4; i++)
#pragma unroll
        for (int j = 0; j < 4; j++) acc2[i][j] = 0ull;

#pragma unroll
    for (int p = 0; p < 4; p++) {
        int i = tid + p * 512;
        int kk = i & 15, bb = i >> 4;
        As[kk * 132 + bb] = Theta[(b0 + bb) * 16384 + spmap[kk]];
    }
#pragma unroll
    for (int p = 0; p < 4; p++) {
        int i = tid + p * 512;
        Bs[i] = g_W1s[(kbase + (i >> 7)) * 128 + (i & 127)];
    }
    __syncthreads();

    float pa[4], pb[4];
    for (int c = 0; c < 17; c++) {
        if (c < 16) {
            int kc = (c + 1) * 16;
#pragma unroll
            for (int p = 0; p < 4; p++) {
                int i = tid + p * 512;
                int kk = i & 15, bb = i >> 4;
                pa[p] = Theta[(b0 + bb) * 16384 + spmap[kc + kk]];
            }
#pragma unroll
            for (int p = 0; p < 4; p++) {
                int i = tid + p * 512;
                pb[p] = g_W1s[(kbase + kc + (i >> 7)) * 128 + (i & 127)];
            }
        }
        const float* Ab = As + (c & 1) * (16 * 132);
        const float* Bb = Bs + (c & 1) * (16 * 128);
#pragma unroll 8
        for (int s = 0; s < 16; s++)
            mma_step512(acc2, Ab + s * 132 + ty * 8, Bb + s * 128 + tx * 4);
        if (c < 16) {
            float* An = As + ((c + 1) & 1) * (16 * 132);
            float* Bn = Bs + ((c + 1) & 1) * (16 * 128);
#pragma unroll
            for (int p = 0; p < 4; p++) {
                int i = tid + p * 512;
                An[(i & 15) * 132 + (i >> 4)] = pa[p];
            }
#pragma unroll
            for (int p = 0; p < 4; p++) {
                int i = tid + p * 512;
                Bn[i] = pb[p];
            }
            __syncthreads();
        }
    }
    float* outp = g_z0p + (blockIdx.y * 1024 + b0) * 128;
#pragma unroll
    for (int i2 = 0; i2 < 4; i2++) {
        float lo[4], hi[4];
#pragma unroll
        for (int j = 0; j < 4; j++) unpack2(acc2[i2][j], lo[j], hi[j]);
        float* p0 = outp + (ty * 8 + 2 * i2) * 128 + tx * 4;
        *(float4*)p0         = make_float4(lo[0], lo[1], lo[2], lo[3]);
        *(float4*)(p0 + 128) = make_float4(hi[0], hi[1], hi[2], hi[3]);
    }
}

// ---------------------------------------------------------------------------
// reduce split-K partials + bias
// ---------------------------------------------------------------------------
__global__ void k_z0red(const float* __restrict__ b1) {
    int idx = blockIdx.x * 256 + threadIdx.x;
    int k = idx & 127;
    float s = (k < 127) ? b1[k] : 0.f;
#pragma unroll
    for (int sp = 0; sp < 32; sp++) s += g_z0p[sp * 131072 + idx];
    g_z0[idx] = s;
}

// ---------------------------------------------------------------------------
// dz[b,t,k] = sum_s D[b,t,s]*U[t,s,k]; D on the fly (diag special case!)
// 8x8 tile, 256-row b-tiles: grid (127, 4), 512 threads, 1 block/SM.
// smem: U 128x128 (64KB) + 2 x 32x264 D tiles (66KB) = 130KB.
// ---------------------------------------------------------------------------
__global__ void __launch_bounds__(512, 1) k_dz(const float* __restrict__ Theta) {
    extern __shared__ float sm[];
    float* Us = sm;            // 128*128 (row 127 zeroed)
    float* Ds = sm + 16384;    // 2 * 32*264, [s][b] pad 264
    const int tid = threadIdx.x, tx = tid & 15, ty = tid >> 4;
    const int t = blockIdx.x, b0 = blockIdx.y * 256;

    {
        const float4* Usrc = (const float4*)(g_Upad + t * 16256);
        float4* Ud = (float4*)Us;
        for (int i = tid; i < 4064; i += 512) Ud[i] = Usrc[i];
        for (int i = 16256 + tid; i < 16384; i += 512) Us[i] = 0.f;
    }

    auto loadD = [&](int c, int p) -> float {
        int i = tid + p * 512;            // 0..8191
        int s = i & 31, bb = i >> 5;      // bb 0..255
        int sg = c * 32 + s;
        if (sg >= 127) return 0.f;
        const float* Tb = Theta + (size_t)(b0 + bb) * 16384;
        if (sg == t)
            return Tb[(t << 7) + t] - Tb[((t + 1) << 7) + (t + 1)];
        int g = sg + (sg >= t);
        return Tb[(t << 7) + g] - Tb[((t + 1) << 7) + g];
    };

#pragma unroll
    for (int p = 0; p < 16; p++) {
        int i = tid + p * 512;
        Ds[(i & 31) * 264 + (i >> 5)] = loadD(0, p);
    }
    __syncthreads();

    ull acc2[4][8];
#pragma unroll
    for (int i = 0; i < 4; i++)
#pragma unroll
        for (int j = 0; j < 8; j++) acc2[i][j] = 0ull;

    float pre[16];
    for (int c = 0; c < 4; c++) {
        if (c < 3) {
#pragma unroll
            for (int p = 0; p < 16; p++) pre[p] = loadD(c + 1, p);
        }
        const float* Db = Ds + (c & 1) * 8448;
        const float* Ub = Us + c * 32 * 128;
#pragma unroll 8
        for (int s = 0; s < 32; s++)
            mma_step88(acc2, Db + s * 264 + ty * 8, Ub + s * 128 + tx * 8);
        if (c < 3) {
            float* Dn = Ds + ((c + 1) & 1) * 8448;
#pragma unroll
            for (int p = 0; p < 16; p++) {
                int i = tid + p * 512;
                Dn[(i & 31) * 264 + (i >> 5)] = pre[p];
            }
            __syncthreads();
        }
    }
#pragma unroll
    for (int i2 = 0; i2 < 4; i2++) {
        float lo[8], hi[8];
#pragma unroll
        for (int j = 0; j < 8; j++) unpack2(acc2[i2][j], lo[j], hi[j]);
        int bb0 = b0 + ty * 8 + 2 * i2;
        float* p0 = g_dz + ((size_t)bb0 * 127 + t) * 128 + tx * 8;
        float* p1 = g_dz + ((size_t)(bb0 + 1) * 127 + t) * 128 + tx * 8;
        *(float4*)p0       = make_float4(lo[0], lo[1], lo[2], lo[3]);
        *(float4*)(p0 + 4) = make_float4(lo[4], lo[5], lo[6], lo[7]);
        *(float4*)p1       = make_float4(hi[0], hi[1], hi[2], hi[3]);
        *(float4*)(p1 + 4) = make_float4(hi[4], hi[5], hi[6], hi[7]);
    }
}

// ---------------------------------------------------------------------------
// Fused: SEGMENTED prefix+ReLU into smem h_T[k][t], GEMM h@W2 streamed,
// bias, out assembly (Theta symmetry). One block per batch (grid 1024).
// ---------------------------------------------------------------------------
__global__ void __launch_bounds__(512, 2) k_g2out(const float* __restrict__ Theta,
                                                  const float* __restrict__ W2,
                                                  const float* __restrict__ b2,
                                                  float* __restrict__ out) {
    extern __shared__ float sm[];
    float* Ht  = sm;                       // [k][t] pad 132; later t12n stage
    float* Ws  = sm + 128 * 132;           // 2 * 32*128 W2 chunks
    float* car = sm + 128 * 132 + 8192;    // [seg][k] 4*128
    const int tid = threadIdx.x, tx = tid & 31, ty = tid >> 5;
    const int b = blockIdx.x;

    // Phase 0a: all threads load W2 chunk 0 into buffer 0.
#pragma unroll
    for (int p = 0; p < 8; p++) {
        int i = tid + p * 512;
        int kk = i >> 7, ss = i & 127;
        Ws[i] = (ss < 127) ? W2[kk * 127 + ss] : 0.f;
    }

    // Phase 0b: segmented prefix partials. (k, seg) = (tid&127, tid>>7).
    {
        const int k = tid & 127, seg = tid >> 7, T0 = seg * 32;
        const float* dzp = g_dz + (size_t)b * 127 * 128 + k;
        float acc = 0.f;
#pragma unroll 4
        for (int tt = 0; tt < 32; tt++) {
            Ht[k * 132 + T0 + tt] = acc;
            int c = T0 + tt;
            if (c < 127) acc += dzp[c * 128];
        }
        car[seg * 128 + k] = acc;
    }
    __syncthreads();

    // Phase 0c: carries (exclusive scan over 4 segments, per k).
    if (tid < 128) {
        float c0 = g_z0[b * 128 + tid];
        float c1 = c0 + car[0 * 128 + tid];
        float c2 = c1 + car[1 * 128 + tid];
        float c3 = c2 + car[2 * 128 + tid];
        car[0 * 128 + tid] = c0;
        car[1 * 128 + tid] = c1;
        car[2 * 128 + tid] = c2;
        car[3 * 128 + tid] = c3;
    }
    __syncthreads();

    // Phase 0d: add carry + ReLU in place.
    {
        const int k = tid & 127, seg = tid >> 7, T0 = seg * 32;
        float C = car[seg * 128 + k];
#pragma unroll 4
        for (int tt = 0; tt < 32; tt++) {
            float v = C + Ht[k * 132 + T0 + tt];
            Ht[k * 132 + T0 + tt] = fmaxf(v, 0.f);
        }
    }
    __syncthreads();

    ull acc2[4][4];
#pragma unroll
    for (int i = 0; i < 4; i++)
#pragma unroll
        for (int j = 0; j < 4; j++) acc2[i][j] = 0ull;

    float pre[8];
    for (int c = 0; c < 4; c++) {
        if (c < 3) {
#pragma unroll
            for (int p = 0; p < 8; p++) {
                int i = tid + p * 512;
                int kk = (c + 1) * 32 + (i >> 7), ss = i & 127;
                pre[p] = (kk < 127 && ss < 127) ? W2[kk * 127 + ss] : 0.f;
            }
        }
        const float* Wb = Ws + (c & 1) * 4096;
#pragma unroll 8
        for (int s = 0; s < 32; s++)
            mma_step512(acc2, Ht + (c * 32 + s) * 132 + ty * 8, Wb + s * 128 + tx * 4);
        if (c < 3) {
            float* Wn = Ws + ((c + 1) & 1) * 4096;
#pragma unroll
            for (int p = 0; p < 8; p++) {
                int i = tid + p * 512;
                Wn[i] = pre[p];
            }
            __syncthreads();
        }
    }
    __syncthreads();   // all Ht reads done before reuse as stage

    float b2v[4];
#pragma unroll
    for (int j = 0; j < 4; j++) {
        int ss = tx * 4 + j;
        b2v[j] = (ss < 127) ? b2[ss] : 0.f;
    }

    // stage t12n tile into Ht: [r][132] (rows = t, cols = s)
#pragma unroll
    for (int i2 = 0; i2 < 4; i2++) {
        float lo[4], hi[4];
#pragma unroll
        for (int j = 0; j < 4; j++) unpack2(acc2[i2][j], lo[j], hi[j]);
        int r0 = ty * 8 + 2 * i2;
#pragma unroll
        for (int j = 0; j < 4; j++) {
            Ht[r0 * 132 + tx * 4 + j]       = lo[j] + b2v[j];
            Ht[(r0 + 1) * 132 + tx * 4 + j] = hi[j] + b2v[j];
        }
    }
    __syncthreads();

    // out[b,r,c]: diag = th; off-diag = th + 129*(t12n[max][min] - th)
    const float* Tb = Theta + (size_t)b * 16384;
    float* Ob = out + (size_t)b * 16384;
    for (int idx4 = tid; idx4 < 4096; idx4 += 512) {
        int r = idx4 >> 5;
        int c0 = (idx4 & 31) * 4;
        float4 th4 = *(const float4*)(Tb + r * 128 + c0);
        float th[4] = {th4.x, th4.y, th4.z, th4.w};
        float o[4];
#pragma unroll
        for (int l = 0; l < 4; l++) {
            int c = c0 + l;
            if (r == c) {
                o[l] = th[l];
            } else {
                int T = r > c ? r : c;
                int m = r < c ? r : c;
                float tn = Ht[T * 132 + m];
                o[l] = th[l] + 129.f * (tn - th[l]);
            }
        }
        *(float4*)(Ob + r * 128 + c0) = make_float4(o[0], o[1], o[2], o[3]);
    }
}

// ---------------------------------------------------------------------------
// Launch: R11 structure — fork z0 chain onto aux stream under dz; join;
// then g2out. (Quarter-pipelining reverted: dz/g2out co-residency is
// LDS-bound and regressed.)
// ---------------------------------------------------------------------------
extern "C" void kernel_launch(void* const* d_in, const int* in_sizes, int n_in,
                              void* d_out, int out_size) {
    const float* Theta = (const float*)d_in[0];
    const float* W1    = (const float*)d_in[1];
    const float* b1    = (const float*)d_in[2];
    const float* W2    = (const float*)d_in[3];
    const float* b2    = (const float*)d_in[4];
    float* out = (float*)d_out;
    (void)in_sizes; (void)n_in; (void)out_size;

    static cudaStream_t s_aux = nullptr;
    static cudaEvent_t ev_root = nullptr, ev_aux = nullptr;
    if (s_aux == nullptr) {                 // first call is outside capture
        cudaStreamCreateWithFlags(&s_aux, cudaStreamNonBlocking);
        cudaEventCreateWithFlags(&ev_root, cudaEventDisableTiming);
        cudaEventCreateWithFlags(&ev_aux, cudaEventDisableTiming);
    }

    const int SM_Z0 = (2 * 16 * 132 + 2 * 16 * 128) * 4 + KPER * 4;
    const int SM_DZ = (16384 + 2 * 32 * 264) * 4;                    // 133120
    const int SM_G2 = (128 * 132 + 2 * 32 * 128 + 512) * 4;          // 102400
    cudaFuncSetAttribute(k_z0s,   cudaFuncAttributeMaxDynamicSharedMemorySize, SM_Z0);
    cudaFuncSetAttribute(k_dz,    cudaFuncAttributeMaxDynamicSharedMemorySize, SM_DZ);
    cudaFuncSetAttribute(k_g2out, cudaFuncAttributeMaxDynamicSharedMemorySize, SM_G2);

    k_build<<<640, 128>>>(W1);

    // fork: aux stream runs the z0 chain concurrently with dz
    cudaEventRecord(ev_root, 0);
    cudaStreamWaitEvent(s_aux, ev_root, 0);
    k_z0s<<<dim3(8, 32), 512, SM_Z0, s_aux>>>(Theta);
    k_z0red<<<512, 256, 0, s_aux>>>(b1);
    cudaEventRecord(ev_aux, s_aux);

    k_dz<<<dim3(127, 4), 512, SM_DZ>>>(Theta);

    // join
    cudaStreamWaitEvent(0, ev_aux, 0);
    k_g2out<<<1024, 512, SM_G2>>>(Theta, W2, b2, out);
}

// round 14
// speedup vs baseline: 1.3208x; 1.3208x over previous
#include <cuda_runtime.h>

#define BB 1024
#define PP 128
#define MM 127

typedef unsigned long long ull;

#define NPAIR 8256          // 128*129/2
#define KSPLIT 32
#define KPER 272            // per-split pair count (17 chunks of 16); 32*272 = 8704
#define NPAD (KSPLIT * KPER)

// ---------------------------------------------------------------------------
// Static device scratch (allocation-free)
// ---------------------------------------------------------------------------
__device__ float g_Upad[127 * 127 * 128];     // [t][s][k-pad]   8.3 MB
__device__ float g_W1s[NPAD * 128];           // [pair][k-pad]   4.5 MB (sym-folded)
__device__ int   g_pmap[NPAD];                // pair -> i*128+j (pad -> 0)
__device__ float g_z0p[32 * 1024 * 128];      // split-K partials
__device__ float g_z0[1024 * 128];            // [b][k-pad]
__device__ float g_dz[1024 * 127 * 128];      // [b][t][k-pad]  66.6 MB

// ---------------------------------------------------------------------------
// f32x2 packed-FMA helpers
// ---------------------------------------------------------------------------
__device__ __forceinline__ ull dup2(float x) {
    ull u; asm("mov.b64 %0, {%1, %1};" : "=l"(u) : "r"(__float_as_uint(x))); return u;
}
__device__ __forceinline__ void unpack2(ull u, float& lo, float& hi) {
    unsigned int a, b;
    asm("mov.b64 {%0, %1}, %2;" : "=r"(a), "=r"(b) : "l"(u));
    lo = __uint_as_float(a); hi = __uint_as_float(b);
}
__device__ __forceinline__ void fma2(ull& d, ull a, ull b) {
    asm("fma.rn.f32x2 %0, %1, %2, %0;" : "+l"(d) : "l"(a), "l"(b));
}

// 8 rows x 4 cols per-thread step. Arow/Bcol 16B-aligned smem pointers.
// acc2[i2][j]: rows base+2*i2{,+1}, col base+j.
__device__ __forceinline__ void mma_step512(ull acc2[4][4],
                                            const float* __restrict__ Arow,
                                            const float* __restrict__ Bcol) {
    ulonglong2 aA = *(const ulonglong2*)(Arow);
    ulonglong2 aB = *(const ulonglong2*)(Arow + 4);
    float4 b = *(const float4*)(Bcol);
    ull a2[4] = {aA.x, aA.y, aB.x, aB.y};
    ull bd[4] = {dup2(b.x), dup2(b.y), dup2(b.z), dup2(b.w)};
#pragma unroll
    for (int i2 = 0; i2 < 4; i2++)
#pragma unroll
        for (int j = 0; j < 4; j++) fma2(acc2[i2][j], a2[i2], bd[j]);
}

// ---------------------------------------------------------------------------
// Builder A: U[t][s][k] (508 blocks) — feeds dz (main stream)
// ---------------------------------------------------------------------------
__global__ void k_build_U(const float* __restrict__ W1) {
    int t = blockIdx.x % 127;
    int s0 = (blockIdx.x / 127) * 32;
    int s1 = s0 + 32 < 127 ? s0 + 32 : 127;
    int k = threadIdx.x;
    float winf = (k < MM) ? W1[16256 * 127 + k] : 0.f;
    for (int s = s0; s < s1; s++) {
        float u = 0.f;
        if (k < MM) {
            if (s == t)
                u = W1[(t * 127 + t) * 127 + k] - winf;
            else
                u = W1[(t * 127 + s) * 127 + k]
                  + W1[(s * 127 + t) * 127 + k]
                  - W1[(16129 + s) * 127 + k];
        }
        g_Upad[(t * 127 + s) * 128 + k] = u;
    }
}

// ---------------------------------------------------------------------------
// Builder B: W1s (sym-folded) + pmap (132 blocks) — feeds z0s (aux stream)
// ---------------------------------------------------------------------------
__global__ void k_build_W(const float* __restrict__ W1) {
    int bx = blockIdx.x;
    int k = threadIdx.x;
    if (bx < 128) {
        int i = bx;
        int base = i * 128 - (i * (i - 1)) / 2;
        for (int j = i; j < 128; j++) {
            int p = base + (j - i);
            float v = 0.f;
            if (k < 127) {
                if (i == 0 && j == 0)      v = W1[16256 * 127 + k];
                else if (i == 0)           v = W1[(16129 + j - 1) * 127 + k];
                else if (i == j)           v = W1[((i - 1) * 127 + (i - 1)) * 127 + k];
                else                       v = W1[((i - 1) * 127 + (j - 1)) * 127 + k]
                                             + W1[((j - 1) * 127 + (i - 1)) * 127 + k];
            }
            g_W1s[p * 128 + k] = v;
        }
        for (int p = NPAIR + i; p < NPAD; p += 128)
            g_W1s[p * 128 + k] = 0.f;
    } else {
        int i = (bx - 128) * 32 + (k >> 2);
        int lane = k & 3;
        if (i < 128) {
            int base = i * 128 - (i * (i - 1)) / 2;
            for (int j = i + lane; j < 128; j += 4)
                g_pmap[base + (j - i)] = i * 128 + j;
        }
        if (bx == 128) {
            for (int p = NPAIR + k; p < NPAD; p += 128) g_pmap[p] = 0;
        }
    }
}

// ---------------------------------------------------------------------------
// z0 GEMM (symmetric-packed): [1024, 8704] @ [8704, 128], split-K=32.
// (unchanged from R11 — fully hidden under dz)
// ---------------------------------------------------------------------------
__global__ void __launch_bounds__(512, 2) k_z0s(const float* __restrict__ Theta) {
    extern __shared__ float sm[];
    float* As = sm;
    float* Bs = sm + 2 * 16 * 132;
    int* spmap = (int*)(sm + 2 * 16 * 132 + 2 * 16 * 128);
    const int tid = threadIdx.x, tx = tid & 31, ty = tid >> 5;
    const int b0 = blockIdx.x * 128;
    const int kbase = blockIdx.y * KPER;

    for (int q = tid; q < KPER; q += 512) spmap[q] = g_pmap[kbase + q];
    __syncthreads();

    ull acc2[4][4];
#pragma unroll
    for (int i = 0; i < 4; i++)
#pragma unroll
        for (int j = 0; j < 4; j++) acc2[i][j] = 0ull;

#pragma unroll
    for (int p = 0; p < 4; p++) {
        int i = tid + p * 512;
        int kk = i & 15, bb = i >> 4;
        As[kk * 132 + bb] = Theta[(b0 + bb) * 16384 + spmap[kk]];
    }
#pragma unroll
    for (int p = 0; p < 4; p++) {
        int i = tid + p * 512;
        Bs[i] = g_W1s[(kbase + (i >> 7)) * 128 + (i & 127)];
    }
    __syncthreads();

    float pa[4], pb[4];
    for (int c = 0; c < 17; c++) {
        if (c < 16) {
            int kc = (c + 1) * 16;
#pragma unroll
            for (int p = 0; p < 4; p++) {
                int i = tid + p * 512;
                int kk = i & 15, bb = i >> 4;
                pa[p] = Theta[(b0 + bb) * 16384 + spmap[kc + kk]];
            }
#pragma unroll
            for (int p = 0; p < 4; p++) {
                int i = tid + p * 512;
                pb[p] = g_W1s[(kbase + kc + (i >> 7)) * 128 + (i & 127)];
            }
        }
        const float* Ab = As + (c & 1) * (16 * 132);
        const float* Bb = Bs + (c & 1) * (16 * 128);
#pragma unroll 8
        for (int s = 0; s < 16; s++)
            mma_step512(acc2, Ab + s * 132 + ty * 8, Bb + s * 128 + tx * 4);
        if (c < 16) {
            float* An = As + ((c + 1) & 1) * (16 * 132);
            float* Bn = Bs + ((c + 1) & 1) * (16 * 128);
#pragma unroll
            for (int p = 0; p < 4; p++) {
                int i = tid + p * 512;
                An[(i & 15) * 132 + (i >> 4)] = pa[p];
            }
#pragma unroll
            for (int p = 0; p < 4; p++) {
                int i = tid + p * 512;
                Bn[i] = pb[p];
            }
            __syncthreads();
        }
    }
    float* outp = g_z0p + (blockIdx.y * 1024 + b0) * 128;
#pragma unroll
    for (int i2 = 0; i2 < 4; i2++) {
        float lo[4], hi[4];
#pragma unroll
        for (int j = 0; j < 4; j++) unpack2(acc2[i2][j], lo[j], hi[j]);
        float* p0 = outp + (ty * 8 + 2 * i2) * 128 + tx * 4;
        *(float4*)p0         = make_float4(lo[0], lo[1], lo[2], lo[3]);
        *(float4*)(p0 + 128) = make_float4(hi[0], hi[1], hi[2], hi[3]);
    }
}

// ---------------------------------------------------------------------------
// reduce split-K partials + bias
// ---------------------------------------------------------------------------
__global__ void k_z0red(const float* __restrict__ b1) {
    int idx = blockIdx.x * 256 + threadIdx.x;
    int k = idx & 127;
    float s = (k < 127) ? b1[k] : 0.f;
#pragma unroll
    for (int sp = 0; sp < 32; sp++) s += g_z0p[sp * 131072 + idx];
    g_z0[idx] = s;
}

// ---------------------------------------------------------------------------
// dz[b,t,k] = sum_s D[b,t,s]*U[t,s,k] — R11 envelope (grid (127,8), 512thr,
// 2 blk/SM) with the 4x4 warp-grid remap (lower LDS traffic, same math).
// ---------------------------------------------------------------------------
__global__ void __launch_bounds__(512, 2) k_dz(const float* __restrict__ Theta) {
    extern __shared__ float sm[];
    float* Us = sm;            // 128*128 (row 127 zeroed)
    float* Ds = sm + 16384;    // 2 * 32*132
    const int tid = threadIdx.x;
    const int w = tid >> 5, lane = tid & 31;
    const int R0 = (w >> 2) * 32 + (lane >> 3) * 8;   // batch-row base
    const int C0 = (w & 3) * 32 + (lane & 7) * 4;     // k-col base
    const int t = blockIdx.x, b0 = blockIdx.y * 128;

    {
        const float4* Usrc = (const float4*)(g_Upad + t * 16256);
        float4* Ud = (float4*)Us;
        for (int i = tid; i < 4064; i += 512) Ud[i] = Usrc[i];
        for (int i = 16256 + tid; i < 16384; i += 512) Us[i] = 0.f;
    }

    auto loadD = [&](int c, int p) -> float {
        int i = tid + p * 512;
        int s = i & 31, bb = i >> 5;
        int sg = c * 32 + s;
        if (sg >= 127) return 0.f;
        const float* Tb = Theta + (size_t)(b0 + bb) * 16384;
        if (sg == t)
            return Tb[(t << 7) + t] - Tb[((t + 1) << 7) + (t + 1)];
        int g = sg + (sg >= t);
        return Tb[(t << 7) + g] - Tb[((t + 1) << 7) + g];
    };

#pragma unroll
    for (int p = 0; p < 8; p++) {
        int i = tid + p * 512;
        Ds[(i & 31) * 132 + (i >> 5)] = loadD(0, p);
    }
    __syncthreads();

    ull acc2[4][4];
#pragma unroll
    for (int i = 0; i < 4; i++)
#pragma unroll
        for (int j = 0; j < 4; j++) acc2[i][j] = 0ull;

    float pre[8];
    for (int c = 0; c < 4; c++) {
        if (c < 3) {
#pragma unroll
            for (int p = 0; p < 8; p++) pre[p] = loadD(c + 1, p);
        }
        const float* Db = Ds + (c & 1) * 4224;
        const float* Ub = Us + c * 32 * 128;
#pragma unroll 8
        for (int s = 0; s < 32; s++)
            mma_step512(acc2, Db + s * 132 + R0, Ub + s * 128 + C0);
        if (c < 3) {
            float* Dn = Ds + ((c + 1) & 1) * 4224;
#pragma unroll
            for (int p = 0; p < 8; p++) {
                int i = tid + p * 512;
                Dn[(i & 31) * 132 + (i >> 5)] = pre[p];
            }
            __syncthreads();
        }
    }
#pragma unroll
    for (int i2 = 0; i2 < 4; i2++) {
        float lo[4], hi[4];
#pragma unroll
        for (int j = 0; j < 4; j++) unpack2(acc2[i2][j], lo[j], hi[j]);
        int bb0 = b0 + R0 + 2 * i2;
        float* p0 = g_dz + ((size_t)bb0 * 127 + t) * 128 + C0;
        float* p1 = g_dz + ((size_t)(bb0 + 1) * 127 + t) * 128 + C0;
        *(float4*)p0 = make_float4(lo[0], lo[1], lo[2], lo[3]);
        *(float4*)p1 = make_float4(hi[0], hi[1], hi[2], hi[3]);
    }
}

// ---------------------------------------------------------------------------
// Fused: SEGMENTED prefix+ReLU into smem h_T[k][t], GEMM h@W2 streamed with
// 4x4 warp grid + TRIANGLE SKIP (warps with wr<wc produce only never-read
// upper-triangle t12n entries — skip their GEMM loops entirely), bias,
// out assembly (Theta symmetry). One block per batch (grid 1024).
// ---------------------------------------------------------------------------
__global__ void __launch_bounds__(512, 2) k_g2out(const float* __restrict__ Theta,
                                                  const float* __restrict__ W2,
                                                  const float* __restrict__ b2,
                                                  float* __restrict__ out) {
    extern __shared__ float sm[];
    float* Ht  = sm;                       // [k][t] pad 132; later t12n stage
    float* Ws  = sm + 128 * 132;           // 2 * 32*128 W2 chunks
    float* car = sm + 128 * 132 + 8192;    // [seg][k] 4*128
    const int tid = threadIdx.x;
    const int w = tid >> 5, lane = tid & 31;
    const int wr = w >> 2, wc = w & 3;
    const int R0 = wr * 32 + (lane >> 3) * 8;   // t-row base
    const int C0 = wc * 32 + (lane & 7) * 4;    // s-col base
    const bool live = (wr >= wc);               // lower-triangle warp tiles only
    const int b = blockIdx.x;

    // Phase 0a: all threads load W2 chunk 0 into buffer 0.
#pragma unroll
    for (int p = 0; p < 8; p++) {
        int i = tid + p * 512;
        int kk = i >> 7, ss = i & 127;
        Ws[i] = (ss < 127) ? W2[kk * 127 + ss] : 0.f;
    }

    // Phase 0b: segmented prefix partials. (k, seg) = (tid&127, tid>>7).
    {
        const int k = tid & 127, seg = tid >> 7, T0 = seg * 32;
        const float* dzp = g_dz + (size_t)b * 127 * 128 + k;
        float acc = 0.f;
#pragma unroll 4
        for (int tt = 0; tt < 32; tt++) {
            Ht[k * 132 + T0 + tt] = acc;
            int c = T0 + tt;
            if (c < 127) acc += dzp[c * 128];
        }
        car[seg * 128 + k] = acc;
    }
    __syncthreads();

    // Phase 0c: carries (exclusive scan over 4 segments, per k).
    if (tid < 128) {
        float c0 = g_z0[b * 128 + tid];
        float c1 = c0 + car[0 * 128 + tid];
        float c2 = c1 + car[1 * 128 + tid];
        float c3 = c2 + car[2 * 128 + tid];
        car[0 * 128 + tid] = c0;
        car[1 * 128 + tid] = c1;
        car[2 * 128 + tid] = c2;
        car[3 * 128 + tid] = c3;
    }
    __syncthreads();

    // Phase 0d: add carry + ReLU in place.
    {
        const int k = tid & 127, seg = tid >> 7, T0 = seg * 32;
        float C = car[seg * 128 + k];
#pragma unroll 4
        for (int tt = 0; tt < 32; tt++) {
            float v = C + Ht[k * 132 + T0 + tt];
            Ht[k * 132 + T0 + tt] = fmaxf(v, 0.f);
        }
    }
    __syncthreads();

    ull acc2[4][4];
#pragma unroll
    for (int i = 0; i < 4; i++)
#pragma unroll
        for (int j = 0; j < 4; j++) acc2[i][j] = 0ull;

    float pre[8];
    for (int c = 0; c < 4; c++) {
        if (c < 3) {
#pragma unroll
            for (int p = 0; p < 8; p++) {
                int i = tid + p * 512;
                int kk = (c + 1) * 32 + (i >> 7), ss = i & 127;
                pre[p] = (kk < 127 && ss < 127) ? W2[kk * 127 + ss] : 0.f;
            }
        }
        if (live) {
            const float* Wb = Ws + (c & 1) * 4096;
#pragma unroll 8
            for (int s = 0; s < 32; s++)
                mma_step512(acc2, Ht + (c * 32 + s) * 132 + R0, Wb + s * 128 + C0);
        }
        if (c < 3) {
            float* Wn = Ws + ((c + 1) & 1) * 4096;
#pragma unroll
            for (int p = 0; p < 8; p++) {
                int i = tid + p * 512;
                Wn[i] = pre[p];
            }
            __syncthreads();
        }
    }
    __syncthreads();   // all Ht reads done before reuse as stage

    float b2v[4];
#pragma unroll
    for (int j = 0; j < 4; j++) {
        int ss = C0 + j;
        b2v[j] = (ss < 127) ? b2[ss] : 0.f;
    }

    // stage t12n tile into Ht: [r][132] (rows = t, cols = s).
    // Skipped warps stage zeros+bias into never-read upper-triangle cells.
#pragma unroll
    for (int i2 = 0; i2 < 4; i2++) {
        float lo[4], hi[4];
#pragma unroll
        for (int j = 0; j < 4; j++) unpack2(acc2[i2][j], lo[j], hi[j]);
        int r0 = R0 + 2 * i2;
#pragma unroll
        for (int j = 0; j < 4; j++) {
            Ht[r0 * 132 + C0 + j]       = lo[j] + b2v[j];
            Ht[(r0 + 1) * 132 + C0 + j] = hi[j] + b2v[j];
        }
    }
    __syncthreads();

    // out[b,r,c]: diag = th; off-diag = th + 129*(t12n[max][min] - th)
    const float* Tb = Theta + (size_t)b * 16384;
    float* Ob = out + (size_t)b * 16384;
    for (int idx4 = tid; idx4 < 4096; idx4 += 512) {
        int r = idx4 >> 5;
        int c0 = (idx4 & 31) * 4;
        float4 th4 = *(const float4*)(Tb + r * 128 + c0);
        float th[4] = {th4.x, th4.y, th4.z, th4.w};
        float o[4];
#pragma unroll
        for (int l = 0; l < 4; l++) {
            int c = c0 + l;
            if (r == c) {
                o[l] = th[l];
            } else {
                int T = r > c ? r : c;
                int m = r < c ? r : c;
                float tn = Ht[T * 132 + m];
                o[l] = th[l] + 129.f * (tn - th[l]);
            }
        }
        *(float4*)(Ob + r * 128 + c0) = make_float4(o[0], o[1], o[2], o[3]);
    }
}

// ---------------------------------------------------------------------------
// Launch: fork both builders with their consumers.
//   s0   : build_U -> dz
//   s_aux: build_W -> z0s -> z0red
// join; then g2out.
// ---------------------------------------------------------------------------
extern "C" void kernel_launch(void* const* d_in, const int* in_sizes, int n_in,
                              void* d_out, int out_size) {
    const float* Theta = (const float*)d_in[0];
    const float* W1    = (const float*)d_in[1];
    const float* b1    = (const float*)d_in[2];
    const float* W2    = (const float*)d_in[3];
    const float* b2    = (const float*)d_in[4];
    float* out = (float*)d_out;
    (void)in_sizes; (void)n_in; (void)out_size;

    static cudaStream_t s_aux = nullptr;
    static cudaEvent_t ev_root = nullptr, ev_aux = nullptr;
    if (s_aux == nullptr) {                 // first call is outside capture
        cudaStreamCreateWithFlags(&s_aux, cudaStreamNonBlocking);
        cudaEventCreateWithFlags(&ev_root, cudaEventDisableTiming);
        cudaEventCreateWithFlags(&ev_aux, cudaEventDisableTiming);
    }

    const int SM_Z0 = (2 * 16 * 132 + 2 * 16 * 128) * 4 + KPER * 4;
    const int SM_DZ = (16384 + 2 * 32 * 132) * 4;                    // 99328
    const int SM_G2 = (128 * 132 + 2 * 32 * 128 + 512) * 4;          // 102400
    cudaFuncSetAttribute(k_z0s,   cudaFuncAttributeMaxDynamicSharedMemorySize, SM_Z0);
    cudaFuncSetAttribute(k_dz,    cudaFuncAttributeMaxDynamicSharedMemorySize, SM_DZ);
    cudaFuncSetAttribute(k_g2out, cudaFuncAttributeMaxDynamicSharedMemorySize, SM_G2);

    // fork: aux stream builds W1s/pmap then runs the z0 chain
    cudaEventRecord(ev_root, 0);
    cudaStreamWaitEvent(s_aux, ev_root, 0);
    k_build_W<<<132, 128, 0, s_aux>>>(W1);
    k_z0s<<<dim3(8, 32), 512, SM_Z0, s_aux>>>(Theta);
    k_z0red<<<512, 256, 0, s_aux>>>(b1);
    cudaEventRecord(ev_aux, s_aux);

    // main stream: U builder then dz
    k_build_U<<<508, 128>>>(W1);
    k_dz<<<dim3(127, 8), 512, SM_DZ>>>(Theta);

    // join
    cudaStreamWaitEvent(0, ev_aux, 0);
    k_g2out<<<1024, 512, SM_G2>>>(Theta, W2, b2, out);
}

// round 15
// speedup vs baseline: 1.3388x; 1.0136x over previous
#include <cuda_runtime.h>

#define BB 1024
#define PP 128
#define MM 127

typedef unsigned long long ull;

#define NPAIR 8256          // 128*129/2
#define KSPLIT 32
#define KPER 272            // per-split pair count (17 chunks of 16); 32*272 = 8704
#define NPAD (KSPLIT * KPER)

// ---------------------------------------------------------------------------
// Static device scratch (allocation-free)
// ---------------------------------------------------------------------------
__device__ float g_Upad[127 * 127 * 128];     // [t][s][k-pad]   8.3 MB
__device__ float g_W1s[NPAD * 128];           // [pair][k-pad]   4.5 MB (sym-folded)
__device__ int   g_pmap[NPAD];                // pair -> i*128+j (pad -> 0)
__device__ float g_z0p[32 * 1024 * 128];      // split-K partials
__device__ float g_z0[1024 * 128];            // [b][k-pad]
__device__ float g_dz[1024 * 127 * 128];      // [b][t][k-pad]  66.6 MB

// ---------------------------------------------------------------------------
// f32x2 packed-FMA helpers
// ---------------------------------------------------------------------------
__device__ __forceinline__ ull dup2(float x) {
    ull u; asm("mov.b64 %0, {%1, %1};" : "=l"(u) : "r"(__float_as_uint(x))); return u;
}
__device__ __forceinline__ void unpack2(ull u, float& lo, float& hi) {
    unsigned int a, b;
    asm("mov.b64 {%0, %1}, %2;" : "=r"(a), "=r"(b) : "l"(u));
    lo = __uint_as_float(a); hi = __uint_as_float(b);
}
__device__ __forceinline__ void fma2(ull& d, ull a, ull b) {
    asm("fma.rn.f32x2 %0, %1, %2, %0;" : "+l"(d) : "l"(a), "l"(b));
}

// 8 rows x 4 cols per-thread step. Arow/Bcol 16B-aligned smem pointers.
__device__ __forceinline__ void mma_step512(ull acc2[4][4],
                                            const float* __restrict__ Arow,
                                            const float* __restrict__ Bcol) {
    ulonglong2 aA = *(const ulonglong2*)(Arow);
    ulonglong2 aB = *(const ulonglong2*)(Arow + 4);
    float4 b = *(const float4*)(Bcol);
    ull a2[4] = {aA.x, aA.y, aB.x, aB.y};
    ull bd[4] = {dup2(b.x), dup2(b.y), dup2(b.z), dup2(b.w)};
#pragma unroll
    for (int i2 = 0; i2 < 4; i2++)
#pragma unroll
        for (int j = 0; j < 4; j++) fma2(acc2[i2][j], a2[i2], bd[j]);
}

// ---------------------------------------------------------------------------
// Builder A: U[t][s][k] — grid 2032 (t x 16 s-ranges of 8) for latency hiding
// ---------------------------------------------------------------------------
__global__ void k_build_U(const float* __restrict__ W1) {
    int t = blockIdx.x >> 4;               // 0..126
    int s0 = (blockIdx.x & 15) * 8;
    int s1 = s0 + 8 < 127 ? s0 + 8 : 127;
    int k = threadIdx.x;
    float winf = (k < MM) ? W1[16256 * 127 + k] : 0.f;
    for (int s = s0; s < s1; s++) {
        float u = 0.f;
        if (k < MM) {
            if (s == t)
                u = W1[(t * 127 + t) * 127 + k] - winf;
            else
                u = W1[(t * 127 + s) * 127 + k]
                  + W1[(s * 127 + t) * 127 + k]
                  - W1[(16129 + s) * 127 + k];
        }
        g_Upad[(t * 127 + s) * 128 + k] = u;
    }
}

// ---------------------------------------------------------------------------
// Builder B: W1s (sym-folded) + pmap (132 blocks) — feeds z0s (aux stream)
// ---------------------------------------------------------------------------
__global__ void k_build_W(const float* __restrict__ W1) {
    int bx = blockIdx.x;
    int k = threadIdx.x;
    if (bx < 128) {
        int i = bx;
        int base = i * 128 - (i * (i - 1)) / 2;
        for (int j = i; j < 128; j++) {
            int p = base + (j - i);
            float v = 0.f;
            if (k < 127) {
                if (i == 0 && j == 0)      v = W1[16256 * 127 + k];
                else if (i == 0)           v = W1[(16129 + j - 1) * 127 + k];
                else if (i == j)           v = W1[((i - 1) * 127 + (i - 1)) * 127 + k];
                else                       v = W1[((i - 1) * 127 + (j - 1)) * 127 + k]
                                             + W1[((j - 1) * 127 + (i - 1)) * 127 + k];
            }
            g_W1s[p * 128 + k] = v;
        }
        for (int p = NPAIR + i; p < NPAD; p += 128)
            g_W1s[p * 128 + k] = 0.f;
    } else {
        int i = (bx - 128) * 32 + (k >> 2);
        int lane = k & 3;
        if (i < 128) {
            int base = i * 128 - (i * (i - 1)) / 2;
            for (int j = i + lane; j < 128; j += 4)
                g_pmap[base + (j - i)] = i * 128 + j;
        }
        if (bx == 128) {
            for (int p = NPAIR + k; p < NPAD; p += 128) g_pmap[p] = 0;
        }
    }
}

// ---------------------------------------------------------------------------
// z0 GEMM (symmetric-packed): [1024, 8704] @ [8704, 128], split-K=32.
// ---------------------------------------------------------------------------
__global__ void __launch_bounds__(512, 2) k_z0s(const float* __restrict__ Theta) {
    extern __shared__ float sm[];
    float* As = sm;
    float* Bs = sm + 2 * 16 * 132;
    int* spmap = (int*)(sm + 2 * 16 * 132 + 2 * 16 * 128);
    const int tid = threadIdx.x, tx = tid & 31, ty = tid >> 5;
    const int b0 = blockIdx.x * 128;
    const int kbase = blockIdx.y * KPER;

    for (int q = tid; q < KPER; q += 512) spmap[q] = g_pmap[kbase + q];
    __syncthreads();

    ull acc2[4][4];
#pragma unroll
    for (int i = 0; i < 4; i++)
#pragma unroll
        for (int j = 0; j < 4; j++) acc2[i][j] = 0ull;

#pragma unroll
    for (int p = 0; p < 4; p++) {
        int i = tid + p * 512;
        int kk = i & 15, bb = i >> 4;
        As[kk * 132 + bb] = Theta[(b0 + bb) * 16384 + spmap[kk]];
    }
#pragma unroll
    for (int p = 0; p < 4; p++) {
        int i = tid + p * 512;
        Bs[i] = g_W1s[(kbase + (i >> 7)) * 128 + (i & 127)];
    }
    __syncthreads();

    float pa[4], pb[4];
    for (int c = 0; c < 17; c++) {
        if (c < 16) {
            int kc = (c + 1) * 16;
#pragma unroll
            for (int p = 0; p < 4; p++) {
                int i = tid + p * 512;
                int kk = i & 15, bb = i >> 4;
                pa[p] = Theta[(b0 + bb) * 16384 + spmap[kc + kk]];
            }
#pragma unroll
            for (int p = 0; p < 4; p++) {
                int i = tid + p * 512;
                pb[p] = g_W1s[(kbase + kc + (i >> 7)) * 128 + (i & 127)];
            }
        }
        const float* Ab = As + (c & 1) * (16 * 132);
        const float* Bb = Bs + (c & 1) * (16 * 128);
#pragma unroll 8
        for (int s = 0; s < 16; s++)
            mma_step512(acc2, Ab + s * 132 + (tid >> 5) * 8, Bb + s * 128 + (tid & 31) * 4);
        if (c < 16) {
            float* An = As + ((c + 1) & 1) * (16 * 132);
            float* Bn = Bs + ((c + 1) & 1) * (16 * 128);
#pragma unroll
            for (int p = 0; p < 4; p++) {
                int i = tid + p * 512;
                An[(i & 15) * 132 + (i >> 4)] = pa[p];
            }
#pragma unroll
            for (int p = 0; p < 4; p++) {
                int i = tid + p * 512;
                Bn[i] = pb[p];
            }
            __syncthreads();
        }
    }
    float* outp = g_z0p + (blockIdx.y * 1024 + b0) * 128;
#pragma unroll
    for (int i2 = 0; i2 < 4; i2++) {
        float lo[4], hi[4];
#pragma unroll
        for (int j = 0; j < 4; j++) unpack2(acc2[i2][j], lo[j], hi[j]);
        float* p0 = outp + (ty * 8 + 2 * i2) * 128 + tx * 4;
        *(float4*)p0         = make_float4(lo[0], lo[1], lo[2], lo[3]);
        *(float4*)(p0 + 128) = make_float4(hi[0], hi[1], hi[2], hi[3]);
    }
}

// ---------------------------------------------------------------------------
// reduce split-K partials + bias
// ---------------------------------------------------------------------------
__global__ void k_z0red(const float* __restrict__ b1) {
    int idx = blockIdx.x * 256 + threadIdx.x;
    int k = idx & 127;
    float s = (k < 127) ? b1[k] : 0.f;
#pragma unroll
    for (int sp = 0; sp < 32; sp++) s += g_z0p[sp * 131072 + idx];
    g_z0[idx] = s;
}

// ---------------------------------------------------------------------------
// dz[b,t,k] = sum_s D[b,t,s]*U[t,s,k] — grid (127,8), 512thr, 2 blk/SM,
// 4x4 warp-grid remap.
// ---------------------------------------------------------------------------
__global__ void __launch_bounds__(512, 2) k_dz(const float* __restrict__ Theta) {
    extern __shared__ float sm[];
    float* Us = sm;            // 128*128 (row 127 zeroed)
    float* Ds = sm + 16384;    // 2 * 32*132
    const int tid = threadIdx.x;
    const int w = tid >> 5, lane = tid & 31;
    const int R0 = (w >> 2) * 32 + (lane >> 3) * 8;   // batch-row base
    const int C0 = (w & 3) * 32 + (lane & 7) * 4;     // k-col base
    const int t = blockIdx.x, b0 = blockIdx.y * 128;

    {
        const float4* Usrc = (const float4*)(g_Upad + t * 16256);
        float4* Ud = (float4*)Us;
        for (int i = tid; i < 4064; i += 512) Ud[i] = Usrc[i];
        for (int i = 16256 + tid; i < 16384; i += 512) Us[i] = 0.f;
    }

    auto loadD = [&](int c, int p) -> float {
        int i = tid + p * 512;
        int s = i & 31, bb = i >> 5;
        int sg = c * 32 + s;
        if (sg >= 127) return 0.f;
        const float* Tb = Theta + (size_t)(b0 + bb) * 16384;
        if (sg == t)
            return Tb[(t << 7) + t] - Tb[((t + 1) << 7) + (t + 1)];
        int g = sg + (sg >= t);
        return Tb[(t << 7) + g] - Tb[((t + 1) << 7) + g];
    };

#pragma unroll
    for (int p = 0; p < 8; p++) {
        int i = tid + p * 512;
        Ds[(i & 31) * 132 + (i >> 5)] = loadD(0, p);
    }
    __syncthreads();

    ull acc2[4][4];
#pragma unroll
    for (int i = 0; i < 4; i++)
#pragma unroll
        for (int j = 0; j < 4; j++) acc2[i][j] = 0ull;

    float pre[8];
    for (int c = 0; c < 4; c++) {
        if (c < 3) {
#pragma unroll
            for (int p = 0; p < 8; p++) pre[p] = loadD(c + 1, p);
        }
        const float* Db = Ds + (c & 1) * 4224;
        const float* Ub = Us + c * 32 * 128;
#pragma unroll 8
        for (int s = 0; s < 32; s++)
            mma_step512(acc2, Db + s * 132 + R0, Ub + s * 128 + C0);
        if (c < 3) {
            float* Dn = Ds + ((c + 1) & 1) * 4224;
#pragma unroll
            for (int p = 0; p < 8; p++) {
                int i = tid + p * 512;
                Dn[(i & 31) * 132 + (i >> 5)] = pre[p];
            }
            __syncthreads();
        }
    }
#pragma unroll
    for (int i2 = 0; i2 < 4; i2++) {
        float lo[4], hi[4];
#pragma unroll
        for (int j = 0; j < 4; j++) unpack2(acc2[i2][j], lo[j], hi[j]);
        int bb0 = b0 + R0 + 2 * i2;
        float* p0 = g_dz + ((size_t)bb0 * 127 + t) * 128 + C0;
        float* p1 = g_dz + ((size_t)(bb0 + 1) * 127 + t) * 128 + C0;
        *(float4*)p0 = make_float4(lo[0], lo[1], lo[2], lo[3]);
        *(float4*)p1 = make_float4(hi[0], hi[1], hi[2], hi[3]);
    }
}

// ---------------------------------------------------------------------------
// Fused: segmented prefix+ReLU -> h_T[k][t]; GEMM h@W2 (4x4 warp grid,
// triangle skip); MIRRORED t12n staging (both (r,c) and (c,r)) so the out
// phase reads contiguous conflict-free float4s; out assembly (Theta symmetry).
// ---------------------------------------------------------------------------
__global__ void __launch_bounds__(512, 2) k_g2out(const float* __restrict__ Theta,
                                                  const float* __restrict__ W2,
                                                  const float* __restrict__ b2,
                                                  float* __restrict__ out) {
    extern __shared__ float sm[];
    float* Ht  = sm;                       // [k][t] pad 132; later t12n stage
    float* Ws  = sm + 128 * 132;           // 2 * 32*128 W2 chunks
    float* car = sm + 128 * 132 + 8192;    // [seg][k] 4*128
    const int tid = threadIdx.x;
    const int w = tid >> 5, lane = tid & 31;
    const int wr = w >> 2, wc = w & 3;
    const int R0 = wr * 32 + (lane >> 3) * 8;   // t-row base
    const int C0 = wc * 32 + (lane & 7) * 4;    // s-col base
    const bool live = (wr >= wc);               // lower-triangle warp tiles only
    const int b = blockIdx.x;

    // Phase 0a: all threads load W2 chunk 0 into buffer 0.
#pragma unroll
    for (int p = 0; p < 8; p++) {
        int i = tid + p * 512;
        int kk = i >> 7, ss = i & 127;
        Ws[i] = (ss < 127) ? W2[kk * 127 + ss] : 0.f;
    }

    // Phase 0b: segmented prefix partials. (k, seg) = (tid&127, tid>>7).
    {
        const int k = tid & 127, seg = tid >> 7, T0 = seg * 32;
        const float* dzp = g_dz + (size_t)b * 127 * 128 + k;
        float acc = 0.f;
#pragma unroll 4
        for (int tt = 0; tt < 32; tt++) {
            Ht[k * 132 + T0 + tt] = acc;
            int c = T0 + tt;
            if (c < 127) acc += dzp[c * 128];
        }
        car[seg * 128 + k] = acc;
    }
    __syncthreads();

    // Phase 0c: carries (exclusive scan over 4 segments, per k).
    if (tid < 128) {
        float c0 = g_z0[b * 128 + tid];
        float c1 = c0 + car[0 * 128 + tid];
        float c2 = c1 + car[1 * 128 + tid];
        float c3 = c2 + car[2 * 128 + tid];
        car[0 * 128 + tid] = c0;
        car[1 * 128 + tid] = c1;
        car[2 * 128 + tid] = c2;
        car[3 * 128 + tid] = c3;
    }
    __syncthreads();

    // Phase 0d: add carry + ReLU in place.
    {
        const int k = tid & 127, seg = tid >> 7, T0 = seg * 32;
        float C = car[seg * 128 + k];
#pragma unroll 4
        for (int tt = 0; tt < 32; tt++) {
            float v = C + Ht[k * 132 + T0 + tt];
            Ht[k * 132 + T0 + tt] = fmaxf(v, 0.f);
        }
    }
    __syncthreads();

    ull acc2[4][4];
#pragma unroll
    for (int i = 0; i < 4; i++)
#pragma unroll
        for (int j = 0; j < 4; j++) acc2[i][j] = 0ull;

    float pre[8];
    for (int c = 0; c < 4; c++) {
        if (c < 3) {
#pragma unroll
            for (int p = 0; p < 8; p++) {
                int i = tid + p * 512;
                int kk = (c + 1) * 32 + (i >> 7), ss = i & 127;
                pre[p] = (kk < 127 && ss < 127) ? W2[kk * 127 + ss] : 0.f;
            }
        }
        if (live) {
            const float* Wb = Ws + (c & 1) * 4096;
#pragma unroll 8
            for (int s = 0; s < 32; s++)
                mma_step512(acc2, Ht + (c * 32 + s) * 132 + R0, Wb + s * 128 + C0);
        }
        if (c < 3) {
            float* Wn = Ws + ((c + 1) & 1) * 4096;
#pragma unroll
            for (int p = 0; p < 8; p++) {
                int i = tid + p * 512;
                Wn[i] = pre[p];
            }
            __syncthreads();
        }
    }
    __syncthreads();   // all Ht reads done before reuse as stage

    float b2v[4];
#pragma unroll
    for (int j = 0; j < 4; j++) {
        int ss = C0 + j;
        b2v[j] = (ss < 127) ? b2[ss] : 0.f;
    }

    // Mirrored staging: slot (rr,cc) gets t12n[rr][cc]+b2[cc] for rr>=cc,
    // slot (cc,rr) gets the same value for rr>cc. Dead warps write nothing;
    // upper slots are filled exclusively by mirrors -> no races.
    if (live) {
#pragma unroll
        for (int i2 = 0; i2 < 4; i2++) {
            float lo[4], hi[4];
#pragma unroll
            for (int j = 0; j < 4; j++) unpack2(acc2[i2][j], lo[j], hi[j]);
            int r0 = R0 + 2 * i2;
#pragma unroll
            for (int j = 0; j < 4; j++) {
                int cc = C0 + j;
                float v0 = lo[j] + b2v[j];
                float v1 = hi[j] + b2v[j];
                if (r0 >= cc)     Ht[r0 * 132 + cc] = v0;
                if (r0 > cc)      Ht[cc * 132 + r0] = v0;
                if (r0 + 1 >= cc) Ht[(r0 + 1) * 132 + cc] = v1;
                if (r0 + 1 > cc)  Ht[cc * 132 + (r0 + 1)] = v1;
            }
        }
    }
    __syncthreads();

    // out[b,r,c]: diag = th; off-diag = th + 129*(t12n_sym - th).
    // Ht row reads are contiguous float4 (conflict-free).
    const float* Tb = Theta + (size_t)b * 16384;
    float* Ob = out + (size_t)b * 16384;
    for (int idx4 = tid; idx4 < 4096; idx4 += 512) {
        int r = idx4 >> 5;
        int c0 = (idx4 & 31) * 4;
        float4 th4 = *(const float4*)(Tb + r * 128 + c0);
        float4 tn4 = *(const float4*)(Ht + r * 132 + c0);
        float th[4] = {th4.x, th4.y, th4.z, th4.w};
        float tn[4] = {tn4.x, tn4.y, tn4.z, tn4.w};
        float o[4];
#pragma unroll
        for (int l = 0; l < 4; l++) {
            int c = c0 + l;
            o[l] = (r == c) ? th[l] : th[l] + 129.f * (tn[l] - th[l]);
        }
        *(float4*)(Ob + r * 128 + c0) = make_float4(o[0], o[1], o[2], o[3]);
    }
}

// ---------------------------------------------------------------------------
// Launch: fork both builders with their consumers.
//   s0   : build_U -> dz
//   s_aux: build_W -> z0s -> z0red
// join; then g2out.
// ---------------------------------------------------------------------------
extern "C" void kernel_launch(void* const* d_in, const int* in_sizes, int n_in,
                              void* d_out, int out_size) {
    const float* Theta = (const float*)d_in[0];
    const float* W1    = (const float*)d_in[1];
    const float* b1    = (const float*)d_in[2];
    const float* W2    = (const float*)d_in[3];
    const float* b2    = (const float*)d_in[4];
    float* out = (float*)d_out;
    (void)in_sizes; (void)n_in; (void)out_size;

    static cudaStream_t s_aux = nullptr;
    static cudaEvent_t ev_root = nullptr, ev_aux = nullptr;
    if (s_aux == nullptr) {                 // first call is outside capture
        cudaStreamCreateWithFlags(&s_aux, cudaStreamNonBlocking);
        cudaEventCreateWithFlags(&ev_root, cudaEventDisableTiming);
        cudaEventCreateWithFlags(&ev_aux, cudaEventDisableTiming);
    }

    const int SM_Z0 = (2 * 16 * 132 + 2 * 16 * 128) * 4 + KPER * 4;
    const int SM_DZ = (16384 + 2 * 32 * 132) * 4;                    // 99328
    const int SM_G2 = (128 * 132 + 2 * 32 * 128 + 512) * 4;          // 102400
    cudaFuncSetAttribute(k_z0s,   cudaFuncAttributeMaxDynamicSharedMemorySize, SM_Z0);
    cudaFuncSetAttribute(k_dz,    cudaFuncAttributeMaxDynamicSharedMemorySize, SM_DZ);
    cudaFuncSetAttribute(k_g2out, cudaFuncAttributeMaxDynamicSharedMemorySize, SM_G2);

    // fork: aux stream builds W1s/pmap then runs the z0 chain
    cudaEventRecord(ev_root, 0);
    cudaStreamWaitEvent(s_aux, ev_root, 0);
    k_build_W<<<132, 128, 0, s_aux>>>(W1);
    k_z0s<<<dim3(8, 32), 512, SM_Z0, s_aux>>>(Theta);
    k_z0red<<<512, 256, 0, s_aux>>>(b1);
    cudaEventRecord(ev_aux, s_aux);

    // main stream: U builder (high-concurrency) then dz
    k_build_U<<<2032, 128>>>(W1);
    k_dz<<<dim3(127, 8), 512, SM_DZ>>>(Theta);

    // join
    cudaStreamWaitEvent(0, ev_aux, 0);
    k_g2out<<<1024, 512, SM_G2>>>(Theta, W2, b2, out);
}

// round 16
// speedup vs baseline: 1.3684x; 1.0221x over previous
#include <cuda_runtime.h>
#include <cstdint>

#define BB 1024
#define PP 128
#define MM 127

typedef unsigned long long ull;

#define NPAIR 8256          // 128*129/2
#define KSPLIT 32
#define KPER 272            // per-split pair count (17 chunks of 16); 32*272 = 8704
#define NPAD (KSPLIT * KPER)

// ---------------------------------------------------------------------------
// Static device scratch (allocation-free)
// ---------------------------------------------------------------------------
__device__ float g_Upad[127 * 127 * 128];     // [t][s][k-pad]   8.3 MB
__device__ float g_W1s[NPAD * 128];           // [pair][k-pad]   4.5 MB (sym-folded)
__device__ float g_W2p[128 * 128];            // W2 zero-padded to 128x128
__device__ int   g_pmap[NPAD];                // pair -> i*128+j (pad -> 0)
__device__ float g_z0p[32 * 1024 * 128];      // split-K partials
__device__ float g_z0[1024 * 128];            // [b][k-pad]
__device__ float g_dz[1024 * 127 * 128];      // [b][t][k-pad]  66.6 MB

// ---------------------------------------------------------------------------
// helpers
// ---------------------------------------------------------------------------
__device__ __forceinline__ uint32_t smem_u32(const void* p) {
    uint32_t a;
    asm("{ .reg .u64 t; cvta.to.shared.u64 t, %1; cvt.u32.u64 %0, t; }"
        : "=r"(a) : "l"(p));
    return a;
}
__device__ __forceinline__ void cp_async16(uint32_t dst, const void* src) {
    asm volatile("cp.async.ca.shared.global [%0], [%1], 16;"
                 :: "r"(dst), "l"(src));
}
#define CP_COMMIT() asm volatile("cp.async.commit_group;" ::: "memory")
#define CP_WAIT0()  asm volatile("cp.async.wait_group 0;" ::: "memory")

__device__ __forceinline__ ull dup2(float x) {
    ull u; asm("mov.b64 %0, {%1, %1};" : "=l"(u) : "r"(__float_as_uint(x))); return u;
}
__device__ __forceinline__ void unpack2(ull u, float& lo, float& hi) {
    unsigned int a, b;
    asm("mov.b64 {%0, %1}, %2;" : "=r"(a), "=r"(b) : "l"(u));
    lo = __uint_as_float(a); hi = __uint_as_float(b);
}
__device__ __forceinline__ void fma2(ull& d, ull a, ull b) {
    asm("fma.rn.f32x2 %0, %1, %2, %0;" : "+l"(d) : "l"(a), "l"(b));
}

// 8 rows x 4 cols per-thread step. Arow/Bcol 16B-aligned smem pointers.
__device__ __forceinline__ void mma_step512(ull acc2[4][4],
                                            const float* __restrict__ Arow,
                                            const float* __restrict__ Bcol) {
    ulonglong2 aA = *(const ulonglong2*)(Arow);
    ulonglong2 aB = *(const ulonglong2*)(Arow + 4);
    float4 b = *(const float4*)(Bcol);
    ull a2[4] = {aA.x, aA.y, aB.x, aB.y};
    ull bd[4] = {dup2(b.x), dup2(b.y), dup2(b.z), dup2(b.w)};
#pragma unroll
    for (int i2 = 0; i2 < 4; i2++)
#pragma unroll
        for (int j = 0; j < 4; j++) fma2(acc2[i2][j], a2[i2], bd[j]);
}

// ---------------------------------------------------------------------------
// Builder A: U[t][s][k] — grid 2032 (t x 16 s-ranges of 8)
// ---------------------------------------------------------------------------
__global__ void k_build_U(const float* __restrict__ W1) {
    int t = blockIdx.x >> 4;
    int s0 = (blockIdx.x & 15) * 8;
    int s1 = s0 + 8 < 127 ? s0 + 8 : 127;
    int k = threadIdx.x;
    float winf = (k < MM) ? W1[16256 * 127 + k] : 0.f;
    for (int s = s0; s < s1; s++) {
        float u = 0.f;
        if (k < MM) {
            if (s == t)
                u = W1[(t * 127 + t) * 127 + k] - winf;
            else
                u = W1[(t * 127 + s) * 127 + k]
                  + W1[(s * 127 + t) * 127 + k]
                  - W1[(16129 + s) * 127 + k];
        }
        g_Upad[(t * 127 + s) * 128 + k] = u;
    }
}

// ---------------------------------------------------------------------------
// Builder B: W1s (sym-folded) + pmap + W2p (136 blocks) — aux stream
// ---------------------------------------------------------------------------
__global__ void k_build_W(const float* __restrict__ W1,
                          const float* __restrict__ W2) {
    int bx = blockIdx.x;
    int k = threadIdx.x;
    if (bx < 128) {
        int i = bx;
        int base = i * 128 - (i * (i - 1)) / 2;
        for (int j = i; j < 128; j++) {
            int p = base + (j - i);
            float v = 0.f;
            if (k < 127) {
                if (i == 0 && j == 0)      v = W1[16256 * 127 + k];
                else if (i == 0)           v = W1[(16129 + j - 1) * 127 + k];
                else if (i == j)           v = W1[((i - 1) * 127 + (i - 1)) * 127 + k];
                else                       v = W1[((i - 1) * 127 + (j - 1)) * 127 + k]
                                             + W1[((j - 1) * 127 + (i - 1)) * 127 + k];
            }
            g_W1s[p * 128 + k] = v;
        }
        for (int p = NPAIR + i; p < NPAD; p += 128)
            g_W1s[p * 128 + k] = 0.f;
    } else if (bx < 132) {
        int i = (bx - 128) * 32 + (k >> 2);
        int lane = k & 3;
        if (i < 128) {
            int base = i * 128 - (i * (i - 1)) / 2;
            for (int j = i + lane; j < 128; j += 4)
                g_pmap[base + (j - i)] = i * 128 + j;
        }
        if (bx == 128) {
            for (int p = NPAIR + k; p < NPAD; p += 128) g_pmap[p] = 0;
        }
    } else {
        int base = (bx - 132) * 4096;
        for (int q = 0; q < 32; q++) {
            int i = base + q * 128 + k;
            int kk = i >> 7, ss = i & 127;
            g_W2p[i] = (kk < 127 && ss < 127) ? W2[kk * 127 + ss] : 0.f;
        }
    }
}

// ---------------------------------------------------------------------------
// z0 GEMM (symmetric-packed): [1024, 8704] @ [8704, 128], split-K=32.
// (hidden under dz on the aux stream; unchanged)
// ---------------------------------------------------------------------------
__global__ void __launch_bounds__(512, 2) k_z0s(const float* __restrict__ Theta) {
    extern __shared__ float sm[];
    float* As = sm;
    float* Bs = sm + 2 * 16 * 132;
    int* spmap = (int*)(sm + 2 * 16 * 132 + 2 * 16 * 128);
    const int tid = threadIdx.x, tx = tid & 31, ty = tid >> 5;
    const int b0 = blockIdx.x * 128;
    const int kbase = blockIdx.y * KPER;

    for (int q = tid; q < KPER; q += 512) spmap[q] = g_pmap[kbase + q];
    __syncthreads();

    ull acc2[4][4];
#pragma unroll
    for (int i = 0; i < 4; i++)
#pragma unroll
        for (int j = 0; j < 4; j++) acc2[i][j] = 0ull;

#pragma unroll
    for (int p = 0; p < 4; p++) {
        int i = tid + p * 512;
        int kk = i & 15, bb = i >> 4;
        As[kk * 132 + bb] = Theta[(b0 + bb) * 16384 + spmap[kk]];
    }
#pragma unroll
    for (int p = 0; p < 4; p++) {
        int i = tid + p * 512;
        Bs[i] = g_W1s[(kbase + (i >> 7)) * 128 + (i & 127)];
    }
    __syncthreads();

    float pa[4], pb[4];
    for (int c = 0; c < 17; c++) {
        if (c < 16) {
            int kc = (c + 1) * 16;
#pragma unroll
            for (int p = 0; p < 4; p++) {
                int i = tid + p * 512;
                int kk = i & 15, bb = i >> 4;
                pa[p] = Theta[(b0 + bb) * 16384 + spmap[kc + kk]];
            }
#pragma unroll
            for (int p = 0; p < 4; p++) {
                int i = tid + p * 512;
                pb[p] = g_W1s[(kbase + kc + (i >> 7)) * 128 + (i & 127)];
            }
        }
        const float* Ab = As + (c & 1) * (16 * 132);
        const float* Bb = Bs + (c & 1) * (16 * 128);
#pragma unroll 8
        for (int s = 0; s < 16; s++)
            mma_step512(acc2, Ab + s * 132 + ty * 8, Bb + s * 128 + tx * 4);
        if (c < 16) {
            float* An = As + ((c + 1) & 1) * (16 * 132);
            float* Bn = Bs + ((c + 1) & 1) * (16 * 128);
#pragma unroll
            for (int p = 0; p < 4; p++) {
                int i = tid + p * 512;
                An[(i & 15) * 132 + (i >> 4)] = pa[p];
            }
#pragma unroll
            for (int p = 0; p < 4; p++) {
                int i = tid + p * 512;
                Bn[i] = pb[p];
            }
            __syncthreads();
        }
    }
    float* outp = g_z0p + (blockIdx.y * 1024 + b0) * 128;
#pragma unroll
    for (int i2 = 0; i2 < 4; i2++) {
        float lo[4], hi[4];
#pragma unroll
        for (int j = 0; j < 4; j++) unpack2(acc2[i2][j], lo[j], hi[j]);
        float* p0 = outp + (ty * 8 + 2 * i2) * 128 + tx * 4;
        *(float4*)p0         = make_float4(lo[0], lo[1], lo[2], lo[3]);
        *(float4*)(p0 + 128) = make_float4(hi[0], hi[1], hi[2], hi[3]);
    }
}

// ---------------------------------------------------------------------------
// reduce split-K partials + bias
// ---------------------------------------------------------------------------
__global__ void k_z0red(const float* __restrict__ b1) {
    int idx = blockIdx.x * 256 + threadIdx.x;
    int k = idx & 127;
    float s = (k < 127) ? b1[k] : 0.f;
#pragma unroll
    for (int sp = 0; sp < 32; sp++) s += g_z0p[sp * 131072 + idx];
    g_z0[idx] = s;
}

// ---------------------------------------------------------------------------
// dz[b,t,k] = sum_s D[b,t,s]*U[t,s,k] — grid (127,8), 512thr, 2 blk/SM,
// 4x4 warp grid. U streamed per-chunk via cp.async (double buffered);
// D gathered on the fly (diag special case).
// smem: Ub 2*4096 + Ds 2*4224 floats = 66560 B.
// ---------------------------------------------------------------------------
__global__ void __launch_bounds__(512, 2) k_dz(const float* __restrict__ Theta) {
    extern __shared__ float sm[];
    float* Ub = sm;            // 2 x 32x128 U chunks
    float* Ds = sm + 8192;     // 2 x 32x132 D tiles [s][b]
    const int tid = threadIdx.x;
    const int w = tid >> 5, lane = tid & 31;
    const int R0 = (w >> 2) * 32 + (lane >> 3) * 8;   // batch-row base
    const int C0 = (w & 3) * 32 + (lane & 7) * 4;     // k-col base
    const int t = blockIdx.x, b0 = blockIdx.y * 128;
    const float* Usrc = g_Upad + t * 16256;
    const uint32_t ub_s = smem_u32(Ub);

    auto issueU = [&](int c) {
        int lim = (c == 3) ? 992 : 1024;      // chunk 3 has 31 valid rows
        int buf = (c & 1) * 4096;
#pragma unroll
        for (int p = 0; p < 2; p++) {
            int o = tid + p * 512;
            if (o < lim)
                cp_async16(ub_s + (uint32_t)(buf + o * 4) * 4,
                           Usrc + c * 4096 + o * 4);
        }
        CP_COMMIT();
    };

    auto loadD = [&](int c, int p) -> float {
        int i = tid + p * 512;
        int s = i & 31, bb = i >> 5;
        int sg = c * 32 + s;
        if (sg >= 127) return 0.f;
        const float* Tb = Theta + (size_t)(b0 + bb) * 16384;
        if (sg == t)
            return Tb[(t << 7) + t] - Tb[((t + 1) << 7) + (t + 1)];
        int g = sg + (sg >= t);
        return Tb[(t << 7) + g] - Tb[((t + 1) << 7) + g];
    };

    // prologue: U0 via cp.async, D0 staged directly
    issueU(0);
#pragma unroll
    for (int p = 0; p < 8; p++) {
        int i = tid + p * 512;
        Ds[(i & 31) * 132 + (i >> 5)] = loadD(0, p);
    }
    CP_WAIT0();
    __syncthreads();

    ull acc2[4][4];
#pragma unroll
    for (int i = 0; i < 4; i++)
#pragma unroll
        for (int j = 0; j < 4; j++) acc2[i][j] = 0ull;

    float pre[8];
    for (int c = 0; c < 4; c++) {
        int nx = c + 1;
        if (nx < 4) {
            if (nx == 3 && tid < 32) {   // zero pad row 31 of buffer 1 (s=127)
                float4 z = make_float4(0.f, 0.f, 0.f, 0.f);
                ((float4*)(Ub + 4096 + 31 * 128))[tid] = z;
            }
            issueU(nx);
#pragma unroll
            for (int p = 0; p < 8; p++) pre[p] = loadD(nx, p);
        }
        const float* Db = Ds + (c & 1) * 4224;
        const float* Up = Ub + (c & 1) * 4096;
#pragma unroll 8
        for (int s = 0; s < 32; s++)
            mma_step512(acc2, Db + s * 132 + R0, Up + s * 128 + C0);
        if (nx < 4) {
            float* Dn = Ds + (nx & 1) * 4224;
#pragma unroll
            for (int p = 0; p < 8; p++) {
                int i = tid + p * 512;
                Dn[(i & 31) * 132 + (i >> 5)] = pre[p];
            }
            CP_WAIT0();
            __syncthreads();
        }
    }
#pragma unroll
    for (int i2 = 0; i2 < 4; i2++) {
        float lo[4], hi[4];
#pragma unroll
        for (int j = 0; j < 4; j++) unpack2(acc2[i2][j], lo[j], hi[j]);
        int bb0 = b0 + R0 + 2 * i2;
        float* p0 = g_dz + ((size_t)bb0 * 127 + t) * 128 + C0;
        float* p1 = g_dz + ((size_t)(bb0 + 1) * 127 + t) * 128 + C0;
        *(float4*)p0 = make_float4(lo[0], lo[1], lo[2], lo[3]);
        *(float4*)p1 = make_float4(hi[0], hi[1], hi[2], hi[3]);
    }
}

// ---------------------------------------------------------------------------
// Fused: segmented prefix+ReLU -> h_T[k][t]; GEMM h@W2p (4x4 warp grid,
// triangle skip, W2p streamed via cp.async); mirrored t12n staging;
// out assembly (Theta symmetry). One block per batch (grid 1024).
// ---------------------------------------------------------------------------
__global__ void __launch_bounds__(512, 2) k_g2out(const float* __restrict__ Theta,
                                                  const float* __restrict__ b2,
                                                  float* __restrict__ out) {
    extern __shared__ float sm[];
    float* Ht  = sm;                       // [k][t] pad 132; later t12n stage
    float* Ws  = sm + 128 * 132;           // 2 x 32x128 W2p chunks
    float* car = sm + 128 * 132 + 8192;    // [seg][k] 4*128
    const int tid = threadIdx.x;
    const int w = tid >> 5, lane = tid & 31;
    const int wr = w >> 2, wc = w & 3;
    const int R0 = wr * 32 + (lane >> 3) * 8;   // t-row base
    const int C0 = wc * 32 + (lane & 7) * 4;    // s-col base
    const bool live = (wr >= wc);               // lower-triangle warp tiles
    const int b = blockIdx.x;
    const uint32_t ws_s = smem_u32(Ws);

    auto issueW = [&](int c) {
#pragma unroll
        for (int p = 0; p < 2; p++) {
            int o = tid + p * 512;
            cp_async16(ws_s + (uint32_t)(((c & 1) * 4096 + o * 4)) * 4,
                       g_W2p + c * 4096 + o * 4);
        }
        CP_COMMIT();
    };

    issueW(0);   // W2p chunk 0 streams during the prefix phases

    // Phase 0b: segmented prefix partials with 8-deep batched loads.
    {
        const int k = tid & 127, seg = tid >> 7, T0 = seg * 32;
        const float* dzp = g_dz + (size_t)b * 127 * 128 + k;
        float acc = 0.f;
        float v[8];
#pragma unroll
        for (int h = 0; h < 4; h++) {
#pragma unroll
            for (int q = 0; q < 8; q++) {
                int c = T0 + h * 8 + q;
                v[q] = (c < 127) ? dzp[c * 128] : 0.f;
            }
#pragma unroll
            for (int q = 0; q < 8; q++) {
                Ht[k * 132 + T0 + h * 8 + q] = acc;
                acc += v[q];
            }
        }
        car[seg * 128 + k] = acc;
    }
    __syncthreads();

    // Phase 0c: carries (exclusive scan over 4 segments, per k).
    if (tid < 128) {
        float c0 = g_z0[b * 128 + tid];
        float c1 = c0 + car[0 * 128 + tid];
        float c2 = c1 + car[1 * 128 + tid];
        float c3 = c2 + car[2 * 128 + tid];
        car[0 * 128 + tid] = c0;
        car[1 * 128 + tid] = c1;
        car[2 * 128 + tid] = c2;
        car[3 * 128 + tid] = c3;
    }
    __syncthreads();

    // Phase 0d: add carry + ReLU in place.
    {
        const int k = tid & 127, seg = tid >> 7, T0 = seg * 32;
        float C = car[seg * 128 + k];
#pragma unroll 4
        for (int tt = 0; tt < 32; tt++) {
            float v = C + Ht[k * 132 + T0 + tt];
            Ht[k * 132 + T0 + tt] = fmaxf(v, 0.f);
        }
    }
    CP_WAIT0();      // W2p chunk 0 landed
    __syncthreads();

    ull acc2[4][4];
#pragma unroll
    for (int i = 0; i < 4; i++)
#pragma unroll
        for (int j = 0; j < 4; j++) acc2[i][j] = 0ull;

    for (int c = 0; c < 4; c++) {
        if (c < 3) issueW(c + 1);
        if (live) {
            const float* Wb = Ws + (c & 1) * 4096;
#pragma unroll 8
            for (int s = 0; s < 32; s++)
                mma_step512(acc2, Ht + (c * 32 + s) * 132 + R0, Wb + s * 128 + C0);
        }
        if (c < 3) {
            CP_WAIT0();
            __syncthreads();
        }
    }
    __syncthreads();   // all Ht reads done before reuse as stage

    float b2v[4];
#pragma unroll
    for (int j = 0; j < 4; j++) {
        int ss = C0 + j;
        b2v[j] = (ss < 127) ? b2[ss] : 0.f;
    }

    // Mirrored staging: (rr,cc) for rr>=cc, mirror (cc,rr) for rr>cc.
    if (live) {
#pragma unroll
        for (int i2 = 0; i2 < 4; i2++) {
            float lo[4], hi[4];
#pragma unroll
            for (int j = 0; j < 4; j++) unpack2(acc2[i2][j], lo[j], hi[j]);
            int r0 = R0 + 2 * i2;
#pragma unroll
            for (int j = 0; j < 4; j++) {
                int cc = C0 + j;
                float v0 = lo[j] + b2v[j];
                float v1 = hi[j] + b2v[j];
                if (r0 >= cc)     Ht[r0 * 132 + cc] = v0;
                if (r0 > cc)      Ht[cc * 132 + r0] = v0;
                if (r0 + 1 >= cc) Ht[(r0 + 1) * 132 + cc] = v1;
                if (r0 + 1 > cc)  Ht[cc * 132 + (r0 + 1)] = v1;
            }
        }
    }
    __syncthreads();

    // out[b,r,c]: diag = th; off-diag = th + 129*(t12n_sym - th).
    const float* Tb = Theta + (size_t)b * 16384;
    float* Ob = out + (size_t)b * 16384;
    for (int idx4 = tid; idx4 < 4096; idx4 += 512) {
        int r = idx4 >> 5;
        int c0 = (idx4 & 31) * 4;
        float4 th4 = *(const float4*)(Tb + r * 128 + c0);
        float4 tn4 = *(const float4*)(Ht + r * 132 + c0);
        float th[4] = {th4.x, th4.y, th4.z, th4.w};
        float tn[4] = {tn4.x, tn4.y, tn4.z, tn4.w};
        float o[4];
#pragma unroll
        for (int l = 0; l < 4; l++) {
            int c = c0 + l;
            o[l] = (r == c) ? th[l] : th[l] + 129.f * (tn[l] - th[l]);
        }
        *(float4*)(Ob + r * 128 + c0) = make_float4(o[0], o[1], o[2], o[3]);
    }
}

// ---------------------------------------------------------------------------
// Launch:
//   s0   : build_U -> dz
//   s_aux: build_W -> z0s -> z0red
// join; then g2out.
// ---------------------------------------------------------------------------
extern "C" void kernel_launch(void* const* d_in, const int* in_sizes, int n_in,
                              void* d_out, int out_size) {
    const float* Theta = (const float*)d_in[0];
    const float* W1    = (const float*)d_in[1];
    const float* b1    = (const float*)d_in[2];
    const float* W2    = (const float*)d_in[3];
    const float* b2    = (const float*)d_in[4];
    float* out = (float*)d_out;
    (void)in_sizes; (void)n_in; (void)out_size;

    static cudaStream_t s_aux = nullptr;
    static cudaEvent_t ev_root = nullptr, ev_aux = nullptr;
    if (s_aux == nullptr) {                 // first call is outside capture
        cudaStreamCreateWithFlags(&s_aux, cudaStreamNonBlocking);
        cudaEventCreateWithFlags(&ev_root, cudaEventDisableTiming);
        cudaEventCreateWithFlags(&ev_aux, cudaEventDisableTiming);
    }

    const int SM_Z0 = (2 * 16 * 132 + 2 * 16 * 128) * 4 + KPER * 4;
    const int SM_DZ = (2 * 4096 + 2 * 4224) * 4;                     // 66560
    const int SM_G2 = (128 * 132 + 2 * 32 * 128 + 512) * 4;          // 102400
    cudaFuncSetAttribute(k_z0s,   cudaFuncAttributeMaxDynamicSharedMemorySize, SM_Z0);
    cudaFuncSetAttribute(k_dz,    cudaFuncAttributeMaxDynamicSharedMemorySize, SM_DZ);
    cudaFuncSetAttribute(k_g2out, cudaFuncAttributeMaxDynamicSharedMemorySize, SM_G2);

    // fork: aux stream builds W1s/pmap/W2p then runs the z0 chain
    cudaEventRecord(ev_root, 0);
    cudaStreamWaitEvent(s_aux, ev_root, 0);
    k_build_W<<<136, 128, 0, s_aux>>>(W1, W2);
    k_z0s<<<dim3(8, 32), 512, SM_Z0, s_aux>>>(Theta);
    k_z0red<<<512, 256, 0, s_aux>>>(b1);
    cudaEventRecord(ev_aux, s_aux);

    // main stream: U builder then dz
    k_build_U<<<2032, 128>>>(W1);
    k_dz<<<dim3(127, 8), 512, SM_DZ>>>(Theta);

    // join
    cudaStreamWaitEvent(0, ev_aux, 0);
    k_g2out<<<1024, 512, SM_G2>>>(Theta, b2, out);
}

// round 17
// speedup vs baseline: 1.4346x; 1.0483x over previous
#include <cuda_runtime.h>
#include <cstdint>

#define BB 1024
#define PP 128
#define MM 127

typedef unsigned long long ull;

#define NPAIR 8256          // 128*129/2
#define KSPLIT 32
#define KPER 272            // per-split pair count (17 chunks of 16); 32*272 = 8704
#define NPAD (KSPLIT * KPER)

// ---------------------------------------------------------------------------
// Static device scratch (allocation-free)
// ---------------------------------------------------------------------------
__device__ float g_Upad[127 * 127 * 128];     // [t][s][k-pad]   8.3 MB
__device__ float g_W1s[NPAD * 128];           // [pair][k-pad]   4.5 MB (sym-folded)
__device__ float g_W2p[128 * 128];            // W2 zero-padded to 128x128
__device__ int   g_pmap[NPAD];                // pair -> i*128+j (pad -> 0)
__device__ float g_z0p[32 * 1024 * 128];      // split-K partials
__device__ float g_z0[1024 * 128];            // [b][k-pad]
__device__ float g_dz[1024 * 127 * 128];      // [b][t][k-pad]  66.6 MB

// ---------------------------------------------------------------------------
// helpers
// ---------------------------------------------------------------------------
__device__ __forceinline__ uint32_t smem_u32(const void* p) {
    uint32_t a;
    asm("{ .reg .u64 t; cvta.to.shared.u64 t, %1; cvt.u32.u64 %0, t; }"
        : "=r"(a) : "l"(p));
    return a;
}
__device__ __forceinline__ void cp_async16(uint32_t dst, const void* src) {
    asm volatile("cp.async.ca.shared.global [%0], [%1], 16;"
                 :: "r"(dst), "l"(src));
}
#define CP_COMMIT() asm volatile("cp.async.commit_group;" ::: "memory")
#define CP_WAIT0()  asm volatile("cp.async.wait_group 0;" ::: "memory")

__device__ __forceinline__ ull dup2(float x) {
    ull u; asm("mov.b64 %0, {%1, %1};" : "=l"(u) : "r"(__float_as_uint(x))); return u;
}
__device__ __forceinline__ void unpack2(ull u, float& lo, float& hi) {
    unsigned int a, b;
    asm("mov.b64 {%0, %1}, %2;" : "=r"(a), "=r"(b) : "l"(u));
    lo = __uint_as_float(a); hi = __uint_as_float(b);
}
__device__ __forceinline__ void fma2(ull& d, ull a, ull b) {
    asm("fma.rn.f32x2 %0, %1, %2, %0;" : "+l"(d) : "l"(a), "l"(b));
}

// 8 rows x 4 cols per-thread step. Arow/Bcol 16B-aligned smem pointers.
__device__ __forceinline__ void mma_step512(ull acc2[4][4],
                                            const float* __restrict__ Arow,
                                            const float* __restrict__ Bcol) {
    ulonglong2 aA = *(const ulonglong2*)(Arow);
    ulonglong2 aB = *(const ulonglong2*)(Arow + 4);
    float4 b = *(const float4*)(Bcol);
    ull a2[4] = {aA.x, aA.y, aB.x, aB.y};
    ull bd[4] = {dup2(b.x), dup2(b.y), dup2(b.z), dup2(b.w)};
#pragma unroll
    for (int i2 = 0; i2 < 4; i2++)
#pragma unroll
        for (int j = 0; j < 4; j++) fma2(acc2[i2][j], a2[i2], bd[j]);
}

// ---------------------------------------------------------------------------
// Builder A: U[t][s][k] — grid 2032 (t x 16 s-ranges of 8)
// ---------------------------------------------------------------------------
__global__ void k_build_U(const float* __restrict__ W1) {
    int t = blockIdx.x >> 4;
    int s0 = (blockIdx.x & 15) * 8;
    int s1 = s0 + 8 < 127 ? s0 + 8 : 127;
    int k = threadIdx.x;
    float winf = (k < MM) ? W1[16256 * 127 + k] : 0.f;
    for (int s = s0; s < s1; s++) {
        float u = 0.f;
        if (k < MM) {
            if (s == t)
                u = W1[(t * 127 + t) * 127 + k] - winf;
            else
                u = W1[(t * 127 + s) * 127 + k]
                  + W1[(s * 127 + t) * 127 + k]
                  - W1[(16129 + s) * 127 + k];
        }
        g_Upad[(t * 127 + s) * 128 + k] = u;
    }
}

// ---------------------------------------------------------------------------
// Builder B: W1s (sym-folded) + pmap + W2p (136 blocks) — aux stream
// ---------------------------------------------------------------------------
__global__ void k_build_W(const float* __restrict__ W1,
                          const float* __restrict__ W2) {
    int bx = blockIdx.x;
    int k = threadIdx.x;
    if (bx < 128) {
        int i = bx;
        int base = i * 128 - (i * (i - 1)) / 2;
        for (int j = i; j < 128; j++) {
            int p = base + (j - i);
            float v = 0.f;
            if (k < 127) {
                if (i == 0 && j == 0)      v = W1[16256 * 127 + k];
                else if (i == 0)           v = W1[(16129 + j - 1) * 127 + k];
                else if (i == j)           v = W1[((i - 1) * 127 + (i - 1)) * 127 + k];
                else                       v = W1[((i - 1) * 127 + (j - 1)) * 127 + k]
                                             + W1[((j - 1) * 127 + (i - 1)) * 127 + k];
            }
            g_W1s[p * 128 + k] = v;
        }
        for (int p = NPAIR + i; p < NPAD; p += 128)
            g_W1s[p * 128 + k] = 0.f;
    } else if (bx < 132) {
        int i = (bx - 128) * 32 + (k >> 2);
        int lane = k & 3;
        if (i < 128) {
            int base = i * 128 - (i * (i - 1)) / 2;
            for (int j = i + lane; j < 128; j += 4)
                g_pmap[base + (j - i)] = i * 128 + j;
        }
        if (bx == 128) {
            for (int p = NPAIR + k; p < NPAD; p += 128) g_pmap[p] = 0;
        }
    } else {
        int base = (bx - 132) * 4096;
        for (int q = 0; q < 32; q++) {
            int i = base + q * 128 + k;
            int kk = i >> 7, ss = i & 127;
            g_W2p[i] = (kk < 127 && ss < 127) ? W2[kk * 127 + ss] : 0.f;
        }
    }
}

// ---------------------------------------------------------------------------
// z0 GEMM (symmetric-packed): [1024, 8704] @ [8704, 128], split-K=32.
// ---------------------------------------------------------------------------
__global__ void __launch_bounds__(512, 2) k_z0s(const float* __restrict__ Theta) {
    extern __shared__ float sm[];
    float* As = sm;
    float* Bs = sm + 2 * 16 * 132;
    int* spmap = (int*)(sm + 2 * 16 * 132 + 2 * 16 * 128);
    const int tid = threadIdx.x, tx = tid & 31, ty = tid >> 5;
    const int b0 = blockIdx.x * 128;
    const int kbase = blockIdx.y * KPER;

    for (int q = tid; q < KPER; q += 512) spmap[q] = g_pmap[kbase + q];
    __syncthreads();

    ull acc2[4][4];
#pragma unroll
    for (int i = 0; i < 4; i++)
#pragma unroll
        for (int j = 0; j < 4; j++) acc2[i][j] = 0ull;

#pragma unroll
    for (int p = 0; p < 4; p++) {
        int i = tid + p * 512;
        int kk = i & 15, bb = i >> 4;
        As[kk * 132 + bb] = Theta[(b0 + bb) * 16384 + spmap[kk]];
    }
#pragma unroll
    for (int p = 0; p < 4; p++) {
        int i = tid + p * 512;
        Bs[i] = g_W1s[(kbase + (i >> 7)) * 128 + (i & 127)];
    }
    __syncthreads();

    float pa[4], pb[4];
    for (int c = 0; c < 17; c++) {
        if (c < 16) {
            int kc = (c + 1) * 16;
#pragma unroll
            for (int p = 0; p < 4; p++) {
                int i = tid + p * 512;
                int kk = i & 15, bb = i >> 4;
                pa[p] = Theta[(b0 + bb) * 16384 + spmap[kc + kk]];
            }
#pragma unroll
            for (int p = 0; p < 4; p++) {
                int i = tid + p * 512;
                pb[p] = g_W1s[(kbase + kc + (i >> 7)) * 128 + (i & 127)];
            }
        }
        const float* Ab = As + (c & 1) * (16 * 132);
        const float* Bb = Bs + (c & 1) * (16 * 128);
#pragma unroll 8
        for (int s = 0; s < 16; s++)
            mma_step512(acc2, Ab + s * 132 + ty * 8, Bb + s * 128 + tx * 4);
        if (c < 16) {
            float* An = As + ((c + 1) & 1) * (16 * 132);
            float* Bn = Bs + ((c + 1) & 1) * (16 * 128);
#pragma unroll
            for (int p = 0; p < 4; p++) {
                int i = tid + p * 512;
                An[(i & 15) * 132 + (i >> 4)] = pa[p];
            }
#pragma unroll
            for (int p = 0; p < 4; p++) {
                int i = tid + p * 512;
                Bn[i] = pb[p];
            }
            __syncthreads();
        }
    }
    float* outp = g_z0p + (blockIdx.y * 1024 + b0) * 128;
#pragma unroll
    for (int i2 = 0; i2 < 4; i2++) {
        float lo[4], hi[4];
#pragma unroll
        for (int j = 0; j < 4; j++) unpack2(acc2[i2][j], lo[j], hi[j]);
        float* p0 = outp + (ty * 8 + 2 * i2) * 128 + tx * 4;
        *(float4*)p0         = make_float4(lo[0], lo[1], lo[2], lo[3]);
        *(float4*)(p0 + 128) = make_float4(hi[0], hi[1], hi[2], hi[3]);
    }
}

// ---------------------------------------------------------------------------
// reduce split-K partials + bias
// ---------------------------------------------------------------------------
__global__ void k_z0red(const float* __restrict__ b1) {
    int idx = blockIdx.x * 256 + threadIdx.x;
    int k = idx & 127;
    float s = (k < 127) ? b1[k] : 0.f;
#pragma unroll
    for (int sp = 0; sp < 32; sp++) s += g_z0p[sp * 131072 + idx];
    g_z0[idx] = s;
}

// ---------------------------------------------------------------------------
// dz[b,t,k] = sum_s D[b,t,s]*U[t,s,k] — halved over batch: grid (127,4),
// b_base selects the half. 512thr, 2 blk/SM, 4x4 warp grid, U via cp.async.
// ---------------------------------------------------------------------------
__global__ void __launch_bounds__(512, 2) k_dz(const float* __restrict__ Theta,
                                               int b_base) {
    extern __shared__ float sm[];
    float* Ub = sm;            // 2 x 32x128 U chunks
    float* Ds = sm + 8192;     // 2 x 32x132 D tiles [s][b]
    const int tid = threadIdx.x;
    const int w = tid >> 5, lane = tid & 31;
    const int R0 = (w >> 2) * 32 + (lane >> 3) * 8;   // batch-row base
    const int C0 = (w & 3) * 32 + (lane & 7) * 4;     // k-col base
    const int t = blockIdx.x, b0 = b_base + blockIdx.y * 128;
    const float* Usrc = g_Upad + t * 16256;
    const uint32_t ub_s = smem_u32(Ub);

    auto issueU = [&](int c) {
        int lim = (c == 3) ? 992 : 1024;      // chunk 3 has 31 valid rows
        int buf = (c & 1) * 4096;
#pragma unroll
        for (int p = 0; p < 2; p++) {
            int o = tid + p * 512;
            if (o < lim)
                cp_async16(ub_s + (uint32_t)(buf + o * 4) * 4,
                           Usrc + c * 4096 + o * 4);
        }
        CP_COMMIT();
    };

    auto loadD = [&](int c, int p) -> float {
        int i = tid + p * 512;
        int s = i & 31, bb = i >> 5;
        int sg = c * 32 + s;
        if (sg >= 127) return 0.f;
        const float* Tb = Theta + (size_t)(b0 + bb) * 16384;
        if (sg == t)
            return Tb[(t << 7) + t] - Tb[((t + 1) << 7) + (t + 1)];
        int g = sg + (sg >= t);
        return Tb[(t << 7) + g] - Tb[((t + 1) << 7) + g];
    };

    issueU(0);
#pragma unroll
    for (int p = 0; p < 8; p++) {
        int i = tid + p * 512;
        Ds[(i & 31) * 132 + (i >> 5)] = loadD(0, p);
    }
    CP_WAIT0();
    __syncthreads();

    ull acc2[4][4];
#pragma unroll
    for (int i = 0; i < 4; i++)
#pragma unroll
        for (int j = 0; j < 4; j++) acc2[i][j] = 0ull;

    float pre[8];
    for (int c = 0; c < 4; c++) {
        int nx = c + 1;
        if (nx < 4) {
            if (nx == 3 && tid < 32) {   // zero pad row 31 of buffer 1 (s=127)
                float4 z = make_float4(0.f, 0.f, 0.f, 0.f);
                ((float4*)(Ub + 4096 + 31 * 128))[tid] = z;
            }
            issueU(nx);
#pragma unroll
            for (int p = 0; p < 8; p++) pre[p] = loadD(nx, p);
        }
        const float* Db = Ds + (c & 1) * 4224;
        const float* Up = Ub + (c & 1) * 4096;
#pragma unroll 8
        for (int s = 0; s < 32; s++)
            mma_step512(acc2, Db + s * 132 + R0, Up + s * 128 + C0);
        if (nx < 4) {
            float* Dn = Ds + (nx & 1) * 4224;
#pragma unroll
            for (int p = 0; p < 8; p++) {
                int i = tid + p * 512;
                Dn[(i & 31) * 132 + (i >> 5)] = pre[p];
            }
            CP_WAIT0();
            __syncthreads();
        }
    }
#pragma unroll
    for (int i2 = 0; i2 < 4; i2++) {
        float lo[4], hi[4];
#pragma unroll
        for (int j = 0; j < 4; j++) unpack2(acc2[i2][j], lo[j], hi[j]);
        int bb0 = b0 + R0 + 2 * i2;
        float* p0 = g_dz + ((size_t)bb0 * 127 + t) * 128 + C0;
        float* p1 = g_dz + ((size_t)(bb0 + 1) * 127 + t) * 128 + C0;
        *(float4*)p0 = make_float4(lo[0], lo[1], lo[2], lo[3]);
        *(float4*)p1 = make_float4(hi[0], hi[1], hi[2], hi[3]);
    }
}

// ---------------------------------------------------------------------------
// Fused: segmented prefix+ReLU -> h_T[k][t]; GEMM h@W2p (4x4 warp grid,
// triangle skip, W2p streamed via cp.async); mirrored t12n staging;
// out assembly (Theta symmetry). Halved: grid 512, b_base offset.
// ---------------------------------------------------------------------------
__global__ void __launch_bounds__(512, 2) k_g2out(const float* __restrict__ Theta,
                                                  const float* __restrict__ b2,
                                                  float* __restrict__ out,
                                                  int b_base) {
    extern __shared__ float sm[];
    float* Ht  = sm;                       // [k][t] pad 132; later t12n stage
    float* Ws  = sm + 128 * 132;           // 2 x 32x128 W2p chunks
    float* car = sm + 128 * 132 + 8192;    // [seg][k] 4*128
    const int tid = threadIdx.x;
    const int w = tid >> 5, lane = tid & 31;
    const int wr = w >> 2, wc = w & 3;
    const int R0 = wr * 32 + (lane >> 3) * 8;   // t-row base
    const int C0 = wc * 32 + (lane & 7) * 4;    // s-col base
    const bool live = (wr >= wc);               // lower-triangle warp tiles
    const int b = b_base + blockIdx.x;
    const uint32_t ws_s = smem_u32(Ws);

    auto issueW = [&](int c) {
#pragma unroll
        for (int p = 0; p < 2; p++) {
            int o = tid + p * 512;
            cp_async16(ws_s + (uint32_t)(((c & 1) * 4096 + o * 4)) * 4,
                       g_W2p + c * 4096 + o * 4);
        }
        CP_COMMIT();
    };

    issueW(0);   // W2p chunk 0 streams during the prefix phases

    // Phase 0b: segmented prefix partials with 8-deep batched loads.
    {
        const int k = tid & 127, seg = tid >> 7, T0 = seg * 32;
        const float* dzp = g_dz + (size_t)b * 127 * 128 + k;
        float acc = 0.f;
        float v[8];
#pragma unroll
        for (int h = 0; h < 4; h++) {
#pragma unroll
            for (int q = 0; q < 8; q++) {
                int c = T0 + h * 8 + q;
                v[q] = (c < 127) ? dzp[c * 128] : 0.f;
            }
#pragma unroll
            for (int q = 0; q < 8; q++) {
                Ht[k * 132 + T0 + h * 8 + q] = acc;
                acc += v[q];
            }
        }
        car[seg * 128 + k] = acc;
    }
    __syncthreads();

    // Phase 0c: carries (exclusive scan over 4 segments, per k).
    if (tid < 128) {
        float c0 = g_z0[b * 128 + tid];
        float c1 = c0 + car[0 * 128 + tid];
        float c2 = c1 + car[1 * 128 + tid];
        float c3 = c2 + car[2 * 128 + tid];
        car[0 * 128 + tid] = c0;
        car[1 * 128 + tid] = c1;
        car[2 * 128 + tid] = c2;
        car[3 * 128 + tid] = c3;
    }
    __syncthreads();

    // Phase 0d: add carry + ReLU in place.
    {
        const int k = tid & 127, seg = tid >> 7, T0 = seg * 32;
        float C = car[seg * 128 + k];
#pragma unroll 4
        for (int tt = 0; tt < 32; tt++) {
            float v = C + Ht[k * 132 + T0 + tt];
            Ht[k * 132 + T0 + tt] = fmaxf(v, 0.f);
        }
    }
    CP_WAIT0();      // W2p chunk 0 landed
    __syncthreads();

    ull acc2[4][4];
#pragma unroll
    for (int i = 0; i < 4; i++)
#pragma unroll
        for (int j = 0; j < 4; j++) acc2[i][j] = 0ull;

    for (int c = 0; c < 4; c++) {
        if (c < 3) issueW(c + 1);
        if (live) {
            const float* Wb = Ws + (c & 1) * 4096;
#pragma unroll 8
            for (int s = 0; s < 32; s++)
                mma_step512(acc2, Ht + (c * 32 + s) * 132 + R0, Wb + s * 128 + C0);
        }
        if (c < 3) {
            CP_WAIT0();
            __syncthreads();
        }
    }
    __syncthreads();   // all Ht reads done before reuse as stage

    float b2v[4];
#pragma unroll
    for (int j = 0; j < 4; j++) {
        int ss = C0 + j;
        b2v[j] = (ss < 127) ? b2[ss] : 0.f;
    }

    // Mirrored staging: (rr,cc) for rr>=cc, mirror (cc,rr) for rr>cc.
    if (live) {
#pragma unroll
        for (int i2 = 0; i2 < 4; i2++) {
            float lo[4], hi[4];
#pragma unroll
            for (int j = 0; j < 4; j++) unpack2(acc2[i2][j], lo[j], hi[j]);
            int r0 = R0 + 2 * i2;
#pragma unroll
            for (int j = 0; j < 4; j++) {
                int cc = C0 + j;
                float v0 = lo[j] + b2v[j];
                float v1 = hi[j] + b2v[j];
                if (r0 >= cc)     Ht[r0 * 132 + cc] = v0;
                if (r0 > cc)      Ht[cc * 132 + r0] = v0;
                if (r0 + 1 >= cc) Ht[(r0 + 1) * 132 + cc] = v1;
                if (r0 + 1 > cc)  Ht[cc * 132 + (r0 + 1)] = v1;
            }
        }
    }
    __syncthreads();

    // out[b,r,c]: diag = th; off-diag = th + 129*(t12n_sym - th).
    const float* Tb = Theta + (size_t)b * 16384;
    float* Ob = out + (size_t)b * 16384;
    for (int idx4 = tid; idx4 < 4096; idx4 += 512) {
        int r = idx4 >> 5;
        int c0 = (idx4 & 31) * 4;
        float4 th4 = *(const float4*)(Tb + r * 128 + c0);
        float4 tn4 = *(const float4*)(Ht + r * 132 + c0);
        float th[4] = {th4.x, th4.y, th4.z, th4.w};
        float tn[4] = {tn4.x, tn4.y, tn4.z, tn4.w};
        float o[4];
#pragma unroll
        for (int l = 0; l < 4; l++) {
            int c = c0 + l;
            o[l] = (r == c) ? th[l] : th[l] + 129.f * (tn[l] - th[l]);
        }
        *(float4*)(Ob + r * 128 + c0) = make_float4(o[0], o[1], o[2], o[3]);
    }
}

// ---------------------------------------------------------------------------
// Launch: 2-half software pipeline.
//   s0   : build_U -> dz(h0) [ev_dz0] -> dz(h1) -> (wait ev_z0) g2out(h1)
//          -> (wait ev_g0) done
//   s_aux: build_W -> z0s -> z0red [ev_z0] -> (wait ev_dz0) g2out(h0) [ev_g0]
// ---------------------------------------------------------------------------
extern "C" void kernel_launch(void* const* d_in, const int* in_sizes, int n_in,
                              void* d_out, int out_size) {
    const float* Theta = (const float*)d_in[0];
    const float* W1    = (const float*)d_in[1];
    const float* b1    = (const float*)d_in[2];
    const float* W2    = (const float*)d_in[3];
    const float* b2    = (const float*)d_in[4];
    float* out = (float*)d_out;
    (void)in_sizes; (void)n_in; (void)out_size;

    static cudaStream_t s_aux = nullptr;
    static cudaEvent_t ev_root = nullptr, ev_z0 = nullptr,
                       ev_dz0 = nullptr, ev_g0 = nullptr;
    if (s_aux == nullptr) {                 // first call is outside capture
        cudaStreamCreateWithFlags(&s_aux, cudaStreamNonBlocking);
        cudaEventCreateWithFlags(&ev_root, cudaEventDisableTiming);
        cudaEventCreateWithFlags(&ev_z0, cudaEventDisableTiming);
        cudaEventCreateWithFlags(&ev_dz0, cudaEventDisableTiming);
        cudaEventCreateWithFlags(&ev_g0, cudaEventDisableTiming);
    }

    const int SM_Z0 = (2 * 16 * 132 + 2 * 16 * 128) * 4 + KPER * 4;
    const int SM_DZ = (2 * 4096 + 2 * 4224) * 4;                     // 66560
    const int SM_G2 = (128 * 132 + 2 * 32 * 128 + 512) * 4;          // 102400
    cudaFuncSetAttribute(k_z0s,   cudaFuncAttributeMaxDynamicSharedMemorySize, SM_Z0);
    cudaFuncSetAttribute(k_dz,    cudaFuncAttributeMaxDynamicSharedMemorySize, SM_DZ);
    cudaFuncSetAttribute(k_g2out, cudaFuncAttributeMaxDynamicSharedMemorySize, SM_G2);

    // fork
    cudaEventRecord(ev_root, 0);
    cudaStreamWaitEvent(s_aux, ev_root, 0);

    // aux: builders for z0 path, then z0 chain
    k_build_W<<<136, 128, 0, s_aux>>>(W1, W2);
    k_z0s<<<dim3(8, 32), 512, SM_Z0, s_aux>>>(Theta);
    k_z0red<<<512, 256, 0, s_aux>>>(b1);
    cudaEventRecord(ev_z0, s_aux);

    // main: U builder, then dz half 0
    k_build_U<<<2032, 128>>>(W1);
    k_dz<<<dim3(127, 4), 512, SM_DZ>>>(Theta, 0);
    cudaEventRecord(ev_dz0, 0);

    // aux: g2out half 0 as soon as dz(h0) and z0red are done
    cudaStreamWaitEvent(s_aux, ev_dz0, 0);
    k_g2out<<<512, 512, SM_G2, s_aux>>>(Theta, b2, out, 0);
    cudaEventRecord(ev_g0, s_aux);

    // main: dz half 1, then g2out half 1 (needs z0red)
    k_dz<<<dim3(127, 4), 512, SM_DZ>>>(Theta, 512);
    cudaStreamWaitEvent(0, ev_z0, 0);
    k_g2out<<<512, 512, SM_G2>>>(Theta, b2, out, 512);

    // join
    cudaStreamWaitEvent(0, ev_g0, 0);
}